// round 9
// baseline (speedup 1.0000x reference)
#include <cuda_runtime.h>
#include <cuda_bf16.h>
#include <cstdint>

// Problem constants (fixed for MoELayer_20761871908984)
#define Bq     4
#define Sq     1024
#define Dq     1024
#define Hq     4096
#define Eq     8
#define Kq     2
#define NTOK   (Bq * Sq)        // 4096 tokens
#define MAXROW (NTOK * Kq)      // 8192 max (token, expert) rows
#define MAXTIL 72               // >= sum ceil(cnt_e/128) (bound 71)

// -------- device-global scratch (no runtime allocation allowed) --------
__device__ int   g_counts[Eq];
__device__ int   g_lists[Eq][NTOK];
__device__ int   g_odd_nonzero;              // !=0 -> assign int32; ==0 -> int64
__device__ int   g_tile_e[MAXTIL];
__device__ int   g_tile_m[MAXTIL];
__device__ int   g_base[Eq];
__device__ int   g_ntiles;
// A operands in bulk-copy-ready layout: [tile][kblk][128 rows][36 floats(32+pad)]
__device__ float g_xa[(size_t)MAXTIL * (Dq / 32) * 128 * 36];   // ~42.5 MB
__device__ float g_h [(size_t)MAXTIL * (Hq / 32) * 128 * 36];   // ~170 MB

// ---------------------------------------------------------------------
__global__ void k_zero(float* __restrict__ out, int n) {
    int i = blockIdx.x * blockDim.x + threadIdx.x;
    int stride = gridDim.x * blockDim.x;
    float4 z = make_float4(0.f, 0.f, 0.f, 0.f);
    int n4 = n >> 2;
    for (int j = i; j < n4; j += stride)
        reinterpret_cast<float4*>(out)[j] = z;
    for (int j = (n4 << 2) + i; j < n; j += stride)
        out[j] = 0.f;
    if (i == 0) {
        g_odd_nonzero = 0;
#pragma unroll
        for (int e = 0; e < Eq; e++) g_counts[e] = 0;
    }
}

__global__ void k_detect(const int* __restrict__ a32) {
    int i = blockIdx.x * blockDim.x + threadIdx.x;   // [0, 4096)
    int idx = 2 * i + 1;
    if (idx < NTOK * Kq) {
        if (a32[idx] != 0) atomicOr(&g_odd_nonzero, 1);
    }
}

__global__ void k_build(const int* __restrict__ a32) {
    int t = blockIdx.x * blockDim.x + threadIdx.x;
    if (t >= NTOK) return;
    int is64 = (g_odd_nonzero == 0);
    unsigned mask = 0;
#pragma unroll
    for (int j = 0; j < Kq; j++) {
        int e;
        if (is64) e = a32[(t * Kq + j) * 2];
        else      e = a32[t * Kq + j];
        mask |= 1u << (e & (Eq - 1));
    }
    while (mask) {
        int e = __ffs(mask) - 1;
        mask &= mask - 1;
        int p = atomicAdd(&g_counts[e], 1);
        g_lists[e][p] = t;
    }
}

// Build the (expert, m-tile) work table + per-expert row bases.
__global__ void k_tiles() {
    if (threadIdx.x != 0 || blockIdx.x != 0) return;
    int base = 0, nt = 0;
#pragma unroll
    for (int e = 0; e < Eq; e++) {
        int cnt = g_counts[e];
        g_base[e] = base;
        for (int m0 = 0; m0 < cnt && nt < MAXTIL; m0 += 128) {
            g_tile_e[nt] = e;
            g_tile_m[nt] = m0;
            nt++;
        }
        base += cnt;
    }
    g_ntiles = nt;
}

// ---------------------------------------------------------------------
// tf32 helpers
// ---------------------------------------------------------------------
__device__ __forceinline__ unsigned f2tf32(float f) {
    unsigned r;
    asm volatile("cvt.rna.tf32.f32 %0, %1;\n" : "=r"(r) : "f"(f));
    return r;
}
__device__ __forceinline__ float f2tf32f(float f) {
    return __uint_as_float(f2tf32(f));
}

// Gather + tf32-round x into bulk-ready tiled layout g_xa.
// grid = (Dq/32, MAXTIL), block = 256.
__global__ void k_gather(const float* __restrict__ x) {
    const int ti = blockIdx.y;
    if (ti >= g_ntiles) return;
    const int kb = blockIdx.x;              // 0..31
    const int e   = g_tile_e[ti];
    const int m0  = g_tile_m[ti];
    const int cnt = g_counts[e];
    __shared__ int toks[128];
    if (threadIdx.x < 128) {
        int row = m0 + threadIdx.x;
        toks[threadIdx.x] = (row < cnt) ? g_lists[e][row] : 0;
    }
    __syncthreads();
    float* dst = g_xa + ((size_t)ti * (Dq / 32) + kb) * (128 * 36);
    for (int f = threadIdx.x; f < 128 * 9; f += 256) {
        int r = f / 9, q = f - r * 9;
        float4 v;
        if (q < 8) {
            v = *reinterpret_cast<const float4*>(
                x + (size_t)toks[r] * Dq + kb * 32 + q * 4);
            v.x = f2tf32f(v.x); v.y = f2tf32f(v.y);
            v.z = f2tf32f(v.z); v.w = f2tf32f(v.w);
        } else {
            v = make_float4(0.f, 0.f, 0.f, 0.f);
        }
        *reinterpret_cast<float4*>(dst + (size_t)r * 36 + q * 4) = v;
    }
}

__device__ __forceinline__ void mma_tf32(float& d0, float& d1, float& d2, float& d3,
                                         unsigned a0, unsigned a1, unsigned a2, unsigned a3,
                                         unsigned b0, unsigned b1) {
    asm volatile(
        "mma.sync.aligned.m16n8k8.row.col.f32.tf32.tf32.f32 "
        "{%0,%1,%2,%3},{%4,%5,%6,%7},{%8,%9},{%0,%1,%2,%3};\n"
        : "+f"(d0), "+f"(d1), "+f"(d2), "+f"(d3)
        : "r"(a0), "r"(a1), "r"(a2), "r"(a3), "r"(b0), "r"(b1));
}

__device__ __forceinline__ void ldsm_x4(unsigned& r0, unsigned& r1, unsigned& r2, unsigned& r3,
                                        uint32_t addr) {
    asm volatile("ldmatrix.sync.aligned.m8n8.x4.shared.b16 {%0,%1,%2,%3}, [%4];\n"
                 : "=r"(r0), "=r"(r1), "=r"(r2), "=r"(r3) : "r"(addr));
}

// ---- bulk async copy + mbarrier ----
__device__ __forceinline__ void cp_bulk(uint32_t dst, const void* src,
                                        uint32_t bytes, uint32_t mbar) {
    asm volatile(
        "cp.async.bulk.shared::cta.global.mbarrier::complete_tx::bytes [%0], [%1], %2, [%3];\n"
        :: "r"(dst), "l"(src), "r"(bytes), "r"(mbar) : "memory");
}

#define MBAR_INIT(mbar, cnt) \
    asm volatile("mbarrier.init.shared.b64 [%0], %1;" \
                 :: "r"((uint32_t)(mbar)), "r"((uint32_t)(cnt)) : "memory")
#define MBAR_EXPECT_TX(mbar, bytes) \
    asm volatile("mbarrier.arrive.expect_tx.shared.b64 _, [%0], %1;" \
                 :: "r"((uint32_t)(mbar)), "r"((uint32_t)(bytes)) : "memory")
#define MBAR_ARRIVE(mbar) \
    asm volatile("mbarrier.arrive.shared.b64 _, [%0];" \
                 :: "r"((uint32_t)(mbar)) : "memory")
#define FENCE_PROXY() asm volatile("fence.proxy.async.shared::cta;" ::: "memory")

#define MBAR_WAIT(mbar, parity) do {                                          \
    uint32_t _m = (uint32_t)(mbar);                                           \
    uint32_t _p = (uint32_t)(parity);                                         \
    asm volatile(                                                             \
        "{\n\t.reg .pred P1;\n\t"                                             \
        "WAIT_LOOP_%=:\n\t"                                                   \
        "mbarrier.try_wait.parity.acquire.cta.shared::cta.b64 P1, [%0], %1, 0x989680;\n\t" \
        "@P1 bra.uni WAIT_DONE_%=;\n\t"                                       \
        "bra.uni WAIT_LOOP_%=;\n\t"                                           \
        "WAIT_DONE_%=:\n\t}"                                                  \
        :: "r"(_m), "r"(_p) : "memory");                                      \
} while (0)

// ---------------------------------------------------------------------
// Smem geometry: BK=32 per stage, 3 stages.
// A: [128][36] floats per stage (pad baked into gmem; single 18432B bulk).
// B: [32][136] floats per stage (32 bulk rows of 512B; pad untouched).
// ---------------------------------------------------------------------
#define ASTR 36
#define BSTR 136
#define NSTG 3
#define AFLT (128 * ASTR)                 // 4608 floats
#define BFLT (32 * BSTR)                  // 4352 floats
#define ABYTES (AFLT * 4)                 // 18432
#define BBYTES (32 * 512)                 // 16384 (data bytes only)
#define TXB    (ABYTES + BBYTES)          // 34816
#define OFF_MB   0                        // 6 mbarriers x 8B
#define OFF_TOKS 64
#define OFF_A    1024
#define OFF_B    (OFF_A + NSTG * ABYTES)  // 1024 + 55296
#define SMEM_TOTAL (OFF_B + NSTG * BFLT * 4)   // ~108.5 KB

// ---------------------------------------------------------------------
// tf32 grouped GEMM (mma.sync.m16n8k8), bulk-async staged.
// CTA tile 128x128, BK=32/stage, 256 threads, 8 warps 64x32.
// tid0 = producer (mbarrier expect_tx + cp.async.bulk); all consume.
// ---------------------------------------------------------------------
template<int KD, int ND, bool G1>
__global__ void __launch_bounds__(256, 2)
k_gemm_tc(const float* __restrict__ Ain,      // G1: g_xa ; G2: g_h (tiled layout)
          const float* __restrict__ W,        // RAW fp32 [E][KD][ND]
          const float* __restrict__ bias,
          float* __restrict__ out,
          const int* __restrict__ kp)
{
    constexpr int NK = KD / 32;
    const int ti = blockIdx.y;
    if (ti >= g_ntiles) return;
    const int e   = g_tile_e[ti];
    const int m0  = g_tile_m[ti];
    const int cnt = g_counts[e];
    const int n0  = blockIdx.x * 128;

    extern __shared__ __align__(16) char smem[];
    const uint32_t sb = (uint32_t)__cvta_generic_to_shared(smem);
    int*   toks = reinterpret_cast<int*>(smem + OFF_TOKS);
    float* As   = reinterpret_cast<float*>(smem + OFF_A);
    float* Bs   = reinterpret_cast<float*>(smem + OFF_B);

    const int tid  = threadIdx.x;
    const int lane = tid & 31;
    const int wid  = tid >> 5;
    const int wm   = wid >> 2;     // 0..1
    const int wn   = wid & 3;      // 0..3
    const int g    = lane >> 2;    // 0..7
    const int c    = lane & 3;     // 0..3

    if (!G1 && tid < 128) {        // toks needed only for GEMM2 scatter
        int row = m0 + tid;
        toks[tid] = (row < cnt) ? g_lists[e][row] : 0;
    }
    if (tid == 0) {
#pragma unroll
        for (int s = 0; s < NSTG; s++) {
            MBAR_INIT(sb + OFF_MB + 8 * s, 1);            // full[s]
            MBAR_INIT(sb + OFF_MB + 24 + 8 * s, 256);     // empty[s]
        }
    }
    __syncthreads();

    const float*   Asrc = Ain + (size_t)ti * NK * AFLT;
    const float*   Bsrc = W + (size_t)e * KD * ND + n0;

    int ph_f[NSTG] = {0, 0, 0};
    int ph_e[NSTG] = {1, 1, 1};

    auto produce = [&](int kt, int buf) {
        uint32_t fb = sb + OFF_MB + 8 * buf;
        MBAR_WAIT(sb + OFF_MB + 24 + 8 * buf, ph_e[buf]);
        ph_e[buf] ^= 1;
        FENCE_PROXY();
        MBAR_EXPECT_TX(fb, TXB);
        cp_bulk(sb + OFF_A + buf * ABYTES, Asrc + (size_t)kt * AFLT, ABYTES, fb);
        const float* bs = Bsrc + (size_t)kt * 32 * ND;
#pragma unroll 8
        for (int k = 0; k < 32; k++)
            cp_bulk(sb + OFF_B + buf * (BFLT * 4) + k * (BSTR * 4),
                    bs + (size_t)k * ND, 512, fb);
    };

    float acc[4][4][4];
#pragma unroll
    for (int i = 0; i < 4; i++)
#pragma unroll
        for (int j = 0; j < 4; j++)
#pragma unroll
            for (int r = 0; r < 4; r++) acc[i][j][r] = 0.f;

    if (tid == 0) { produce(0, 0); produce(1, 1); }

    // fragment addressing
    const int lrow = wm * 64 + (lane & 15);
    const int lcol = (lane >> 4) * 4;
    const int bnn0 = wn * 32 + g;

    for (int kt = 0; kt < NK; kt++) {
        const int buf = kt % NSTG;
        if (tid == 0 && kt + 2 < NK) produce(kt + 2, (kt + 2) % NSTG);

        MBAR_WAIT(sb + OFF_MB + 8 * buf, ph_f[buf]);
        ph_f[buf] ^= 1;

        const float* Ab = As + buf * AFLT;
        const float* Bb = Bs + buf * BFLT;

        // fragment double buffers
        unsigned bf0[4][2], bf1[4][2];
        unsigned ac[4], an[4];
#pragma unroll
        for (int j = 0; j < 4; j++) {
            int nn = bnn0 + j * 8;
            bf0[j][0] = f2tf32(Bb[(c) * BSTR + nn]);
            bf0[j][1] = f2tf32(Bb[(c + 4) * BSTR + nn]);
        }
        ldsm_x4(ac[0], ac[1], ac[2], ac[3],
                (uint32_t)__cvta_generic_to_shared(Ab + lrow * ASTR + lcol));

#pragma unroll
        for (int k8 = 0; k8 < 4; k8++) {
            const int kb = k8 * 8;
            unsigned (*bcur)[2] = (k8 & 1) ? bf1 : bf0;
            unsigned (*bnxt)[2] = (k8 & 1) ? bf0 : bf1;
#pragma unroll
            for (int i = 0; i < 4; i++) {
                if (i < 3) {
                    ldsm_x4(an[0], an[1], an[2], an[3],
                            (uint32_t)__cvta_generic_to_shared(
                                Ab + (lrow + (i + 1) * 16) * ASTR + kb + lcol));
                } else if (k8 < 3) {
#pragma unroll
                    for (int j = 0; j < 4; j++) {
                        int nn = bnn0 + j * 8;
                        bnxt[j][0] = f2tf32(Bb[(kb + 8 + c) * BSTR + nn]);
                        bnxt[j][1] = f2tf32(Bb[(kb + 8 + c + 4) * BSTR + nn]);
                    }
                    ldsm_x4(an[0], an[1], an[2], an[3],
                            (uint32_t)__cvta_generic_to_shared(
                                Ab + lrow * ASTR + kb + 8 + lcol));
                }
#pragma unroll
                for (int j = 0; j < 4; j++)
                    mma_tf32(acc[i][j][0], acc[i][j][1], acc[i][j][2], acc[i][j][3],
                             ac[0], ac[1], ac[2], ac[3],
                             bcur[j][0], bcur[j][1]);
#pragma unroll
                for (int r = 0; r < 4; r++) ac[r] = an[r];
            }
        }
        MBAR_ARRIVE(sb + OFF_MB + 24 + 8 * buf);
    }

    // ---- epilogue ----
    if (G1) {
        // relu(acc + b1) -> tf32-round -> g_h in tiled [ti][kblk][128][36] layout
#pragma unroll
        for (int j = 0; j < 4; j++) {
            int col = n0 + wn * 32 + j * 8 + 2 * c;
            float bv0 = __ldg(bias + (size_t)e * ND + col);
            float bv1 = __ldg(bias + (size_t)e * ND + col + 1);
            size_t tbase = ((size_t)ti * (ND / 32) + (col >> 5)) * 128;
            int kin = col & 31;
#pragma unroll
            for (int i = 0; i < 4; i++) {
                int lr0 = wm * 64 + i * 16 + g;
                if (m0 + lr0 < cnt) {
                    float2 v;
                    v.x = f2tf32f(fmaxf(acc[i][j][0] + bv0, 0.f));
                    v.y = f2tf32f(fmaxf(acc[i][j][1] + bv1, 0.f));
                    *reinterpret_cast<float2*>(&g_h[(tbase + lr0) * 36 + kin]) = v;
                }
                int lr1 = lr0 + 8;
                if (m0 + lr1 < cnt) {
                    float2 v;
                    v.x = f2tf32f(fmaxf(acc[i][j][2] + bv0, 0.f));
                    v.y = f2tf32f(fmaxf(acc[i][j][3] + bv1, 0.f));
                    *reinterpret_cast<float2*>(&g_h[(tbase + lr1) * 36 + kin]) = v;
                }
            }
        }
    } else {
        int kv = kp ? __ldg(kp) : Kq;
        if (kv <= 0) kv = Kq;
        float inv_k = 1.0f / (float)kv;
#pragma unroll
        for (int j = 0; j < 4; j++) {
            int col = n0 + wn * 32 + j * 8 + 2 * c;
            float bv0 = __ldg(bias + (size_t)e * ND + col);
            float bv1 = __ldg(bias + (size_t)e * ND + col + 1);
#pragma unroll
            for (int i = 0; i < 4; i++) {
                int lr0 = wm * 64 + i * 16 + g;
                if (m0 + lr0 < cnt) {
                    float* op = out + (size_t)toks[lr0] * ND + col;
                    atomicAdd(op,     (acc[i][j][0] + bv0) * inv_k);
                    atomicAdd(op + 1, (acc[i][j][1] + bv1) * inv_k);
                }
                int lr1 = lr0 + 8;
                if (m0 + lr1 < cnt) {
                    float* op = out + (size_t)toks[lr1] * ND + col;
                    atomicAdd(op,     (acc[i][j][2] + bv0) * inv_k);
                    atomicAdd(op + 1, (acc[i][j][3] + bv1) * inv_k);
                }
            }
        }
    }
}

// ---------------------------------------------------------------------
// launch
// ---------------------------------------------------------------------
extern "C" void kernel_launch(void* const* d_in, const int* in_sizes, int n_in,
                              void* d_out, int out_size) {
    const float* x      = (const float*)d_in[0];
    const float* W1     = (const float*)d_in[1];
    const float* b1     = (const float*)d_in[2];
    const float* W2     = (const float*)d_in[3];
    const float* b2     = (const float*)d_in[4];
    const int*   assign = (const int*)d_in[5];
    const int*   kp     = (n_in >= 7) ? (const int*)d_in[6] : nullptr;
    float* out = (float*)d_out;

    k_zero<<<1024, 256>>>(out, out_size);
    k_detect<<<16, 256>>>(assign);
    k_build<<<16, 256>>>(assign);
    k_tiles<<<1, 32>>>();

    // gather + tf32-round x into bulk-ready tiles
    dim3 gg(Dq / 32, MAXTIL, 1);
    k_gather<<<gg, 256>>>(x);

    float* xa; cudaGetSymbolAddress((void**)&xa, g_xa);
    float* hh; cudaGetSymbolAddress((void**)&hh, g_h);

    cudaFuncSetAttribute(k_gemm_tc<Dq, Hq, true>,
                         cudaFuncAttributeMaxDynamicSharedMemorySize, SMEM_TOTAL);
    cudaFuncSetAttribute(k_gemm_tc<Hq, Dq, false>,
                         cudaFuncAttributeMaxDynamicSharedMemorySize, SMEM_TOTAL);

    // GEMM1: [rows,1024] @ [1024,4096] -> relu -> g_h (tiled, tf32-rounded)
    dim3 g1(Hq / 128, MAXTIL, 1);
    k_gemm_tc<Dq, Hq, true><<<g1, 256, SMEM_TOTAL>>>(xa, W1, b1, nullptr, nullptr);

    // GEMM2: [rows,4096] @ [4096,1024] -> scatter-add out
    dim3 g2(Dq / 128, MAXTIL, 1);
    k_gemm_tc<Hq, Dq, false><<<g2, 256, SMEM_TOTAL>>>(hh, W2, b2, out, kp);
}

// round 10
// speedup vs baseline: 1.2181x; 1.2181x over previous
#include <cuda_runtime.h>
#include <cuda_bf16.h>
#include <cstdint>

// Problem constants (fixed for MoELayer_20761871908984)
#define Bq     4
#define Sq     1024
#define Dq     1024
#define Hq     4096
#define Eq     8
#define Kq     2
#define NTOK   (Bq * Sq)        // 4096 tokens
#define MAXROW (NTOK * Kq)      // 8192 max (token, expert) rows
#define MAXTIL 72               // >= sum ceil(cnt_e/128) (bound 71)

// -------- device-global scratch (no runtime allocation allowed) --------
__device__ int   g_counts[Eq];
__device__ int   g_lists[Eq][NTOK];
__device__ int   g_odd_nonzero;              // !=0 -> assign int32; ==0 -> int64
__device__ int   g_tile_e[MAXTIL];
__device__ int   g_tile_m[MAXTIL];
__device__ int   g_base[Eq];
__device__ int   g_ntiles;
__device__ float g_h[(size_t)MAXROW * Hq];   // hidden activations (tf32-rounded)
__device__ float g_xr[(size_t)NTOK * Dq];    // x, tf32-rounded

// ---------------------------------------------------------------------
__global__ void k_zero(float* __restrict__ out, int n) {
    int i = blockIdx.x * blockDim.x + threadIdx.x;
    int stride = gridDim.x * blockDim.x;
    float4 z = make_float4(0.f, 0.f, 0.f, 0.f);
    int n4 = n >> 2;
    for (int j = i; j < n4; j += stride)
        reinterpret_cast<float4*>(out)[j] = z;
    for (int j = (n4 << 2) + i; j < n; j += stride)
        out[j] = 0.f;
    if (i == 0) {
        g_odd_nonzero = 0;
#pragma unroll
        for (int e = 0; e < Eq; e++) g_counts[e] = 0;
    }
}

__global__ void k_detect(const int* __restrict__ a32) {
    int i = blockIdx.x * blockDim.x + threadIdx.x;   // [0, 4096)
    int idx = 2 * i + 1;
    if (idx < NTOK * Kq) {
        if (a32[idx] != 0) atomicOr(&g_odd_nonzero, 1);
    }
}

__global__ void k_build(const int* __restrict__ a32) {
    int t = blockIdx.x * blockDim.x + threadIdx.x;
    if (t >= NTOK) return;
    int is64 = (g_odd_nonzero == 0);
    unsigned mask = 0;
#pragma unroll
    for (int j = 0; j < Kq; j++) {
        int e;
        if (is64) e = a32[(t * Kq + j) * 2];
        else      e = a32[t * Kq + j];
        mask |= 1u << (e & (Eq - 1));
    }
    while (mask) {
        int e = __ffs(mask) - 1;
        mask &= mask - 1;
        int p = atomicAdd(&g_counts[e], 1);
        g_lists[e][p] = t;
    }
}

// Build the (expert, m-tile) work table + per-expert row bases.
__global__ void k_tiles() {
    if (threadIdx.x != 0 || blockIdx.x != 0) return;
    int base = 0, nt = 0;
#pragma unroll
    for (int e = 0; e < Eq; e++) {
        int cnt = g_counts[e];
        g_base[e] = base;
        for (int m0 = 0; m0 < cnt && nt < MAXTIL; m0 += 128) {
            g_tile_e[nt] = e;
            g_tile_m[nt] = m0;
            nt++;
        }
        base += cnt;
    }
    g_ntiles = nt;
}

// ---------------------------------------------------------------------
// tf32 helpers
// ---------------------------------------------------------------------
__device__ __forceinline__ unsigned f2tf32(float f) {
    unsigned r;
    asm volatile("cvt.rna.tf32.f32 %0, %1;\n" : "=r"(r) : "f"(f));
    return r;
}
__device__ __forceinline__ float f2tf32f(float f) {
    return __uint_as_float(f2tf32(f));
}

// Prepass (x only): dst = tf32_rna(src)
__global__ void k_round4(float* __restrict__ dst, const float* __restrict__ src, int n4) {
    int i = blockIdx.x * blockDim.x + threadIdx.x;
    int stride = gridDim.x * blockDim.x;
    for (; i < n4; i += stride) {
        float4 v = reinterpret_cast<const float4*>(src)[i];
        v.x = f2tf32f(v.x); v.y = f2tf32f(v.y);
        v.z = f2tf32f(v.z); v.w = f2tf32f(v.w);
        reinterpret_cast<float4*>(dst)[i] = v;
    }
}

__device__ __forceinline__ void mma_tf32(float& d0, float& d1, float& d2, float& d3,
                                         unsigned a0, unsigned a1, unsigned a2, unsigned a3,
                                         unsigned b0, unsigned b1) {
    asm volatile(
        "mma.sync.aligned.m16n8k8.row.col.f32.tf32.tf32.f32 "
        "{%0,%1,%2,%3},{%4,%5,%6,%7},{%8,%9},{%0,%1,%2,%3};\n"
        : "+f"(d0), "+f"(d1), "+f"(d2), "+f"(d3)
        : "r"(a0), "r"(a1), "r"(a2), "r"(a3), "r"(b0), "r"(b1));
}

__device__ __forceinline__ void ldsm_x4(unsigned& r0, unsigned& r1, unsigned& r2, unsigned& r3,
                                        uint32_t addr) {
    asm volatile("ldmatrix.sync.aligned.m8n8.x4.shared.b16 {%0,%1,%2,%3}, [%4];\n"
                 : "=r"(r0), "=r"(r1), "=r"(r2), "=r"(r3) : "r"(addr));
}

__device__ __forceinline__ void cp_async16(uint32_t smem_addr, const void* gptr) {
    asm volatile("cp.async.cg.shared.global [%0], [%1], 16;\n"
                 :: "r"(smem_addr), "l"(gptr));
}
__device__ __forceinline__ void cp_commit() { asm volatile("cp.async.commit_group;\n"); }
__device__ __forceinline__ void cp_wait1()  { asm volatile("cp.async.wait_group 1;\n"); }
__device__ __forceinline__ void cp_wait0()  { asm volatile("cp.async.wait_group 0;\n"); }

// ---------------------------------------------------------------------
// Smem geometry: CTA tile 128(M) x 256(N), BK=32, 3 stages, 1 CTA/SM.
// A: [128][ASTR=36]  -> conflict-free LDSM phases (row*36 = 4m mod 32).
// B: [32][BSTR=264]  -> 264 = 8 mod 32; frag lanes 8c+g cover 0..31.
// ---------------------------------------------------------------------
#define ASTR 36
#define BSTR 264
#define NSTG 3
#define A_TILE_FLT (128 * ASTR)            // 4608
#define B_TILE_FLT (32 * BSTR)             // 8448
#define OFF_TOKS   0
#define OFF_A      512
#define OFF_B      (OFF_A + NSTG * A_TILE_FLT * 4)
#define SMEM_TOTAL (OFF_B + NSTG * B_TILE_FLT * 4)   // ~154 KB

// ---------------------------------------------------------------------
// tf32 grouped GEMM (mma.sync.m16n8k8).
// 8 warps of 64x64 (wm 0..1, wn 0..3). cp.async staging for both operands.
// B is raw W; cvt.rna at fragment load (rounding points unchanged).
// ---------------------------------------------------------------------
template<int KD, int ND, bool G1>
__global__ void __launch_bounds__(256, 1)
k_gemm_tc(const float* __restrict__ Ain,      // G1: g_xr ; G2: g_h
          const float* __restrict__ W,        // RAW fp32 [E][KD][ND]
          const float* __restrict__ bias,
          float* __restrict__ out,
          const int* __restrict__ kp)
{
    constexpr int NK = KD / 32;
    const int ti = blockIdx.y;
    if (ti >= g_ntiles) return;
    const int e    = g_tile_e[ti];
    const int m0   = g_tile_m[ti];
    const int cnt  = g_counts[e];
    const int base = g_base[e];
    const int n0   = blockIdx.x * 256;

    extern __shared__ __align__(16) char smem[];
    int*   toks = reinterpret_cast<int*>(smem + OFF_TOKS);
    float* As   = reinterpret_cast<float*>(smem + OFF_A);
    float* Bs   = reinterpret_cast<float*>(smem + OFF_B);

    const int tid  = threadIdx.x;
    const int lane = tid & 31;
    const int wid  = tid >> 5;
    const int wm   = wid >> 2;     // 0..1  (64-row band)
    const int wn   = wid & 3;      // 0..3  (64-col band)
    const int g    = lane >> 2;    // 0..7
    const int c    = lane & 3;     // 0..3

    if (tid < 128) {
        int row = m0 + tid;
        toks[tid] = (row < cnt) ? g_lists[e][row] : 0;
    }
    __syncthreads();

    // ---- A staging (cp.async): 4 chunks/thread ----
    const int aq = tid & 7;
    const float* aSrc[4];
    uint32_t aDst[4];
#pragma unroll
    for (int i = 0; i < 4; i++) {
        int m = (tid >> 3) + 32 * i;
        int row = m0 + m;
        if (G1) aSrc[i] = Ain + (size_t)toks[m] * KD + 4 * aq;
        else    aSrc[i] = g_h + (size_t)((row < cnt) ? base + row : base) * KD + 4 * aq;
        aDst[i] = (uint32_t)((m * ASTR + 4 * aq) * 4);
    }
    // ---- B staging (cp.async, raw W): 8 chunks/thread ----
    // chunk ch = tid + 256*i : k = ch>>6 (0..31), nq = ch&63
    const int bnq = tid & 63;
    const int bk0 = tid >> 6;     // 0..3, +4*i
    const float* Wp = W + (size_t)e * KD * ND;
    const uint32_t sbA = (uint32_t)__cvta_generic_to_shared(As);
    const uint32_t sbB = (uint32_t)__cvta_generic_to_shared(Bs);

    auto load_stage = [&](int kt, int buf) {
        const int k0 = kt * 32;
        const uint32_t dA = sbA + buf * A_TILE_FLT * 4;
        const uint32_t dB = sbB + buf * B_TILE_FLT * 4;
#pragma unroll
        for (int i = 0; i < 4; i++)
            cp_async16(dA + aDst[i], aSrc[i] + k0);
#pragma unroll
        for (int i = 0; i < 8; i++) {
            int k = bk0 + 4 * i;
            cp_async16(dB + (uint32_t)((k * BSTR + 4 * bnq) * 4),
                       Wp + (size_t)(k0 + k) * ND + n0 + 4 * bnq);
        }
        cp_commit();
    };

    float acc[4][8][4];
#pragma unroll
    for (int i = 0; i < 4; i++)
#pragma unroll
        for (int j = 0; j < 8; j++)
#pragma unroll
            for (int r = 0; r < 4; r++) acc[i][j][r] = 0.f;

    load_stage(0, 0);
    load_stage(1, 1);

    // fragment addressing
    const int lrow = wm * 64 + (lane & 15);
    const int lcol = (lane >> 4) * 4;
    const int bnn0 = wn * 64 + g;

    for (int kt = 0; kt < NK; kt++) {
        const int buf = kt % NSTG;
        if (kt + 1 < NK) cp_wait1(); else cp_wait0();
        __syncthreads();
        if (kt + 2 < NK) load_stage(kt + 2, (kt + 2) % NSTG);

        const float* Ab = As + buf * A_TILE_FLT;
        const float* Bb = Bs + buf * B_TILE_FLT;

#pragma unroll
        for (int k8 = 0; k8 < 4; k8++) {
            const int kb = k8 * 8;
            // B fragments: 16 conflict-free LDS + CVT
            unsigned bf[8][2];
#pragma unroll
            for (int j = 0; j < 8; j++) {
                int nn = bnn0 + j * 8;
                bf[j][0] = f2tf32(Bb[(kb + c) * BSTR + nn]);
                bf[j][1] = f2tf32(Bb[(kb + c + 4) * BSTR + nn]);
            }
            // A fragments + MMA
#pragma unroll
            for (int i = 0; i < 4; i++) {
                unsigned a0, a1, a2, a3;
                ldsm_x4(a0, a1, a2, a3,
                        (uint32_t)__cvta_generic_to_shared(
                            Ab + (lrow + i * 16) * ASTR + kb + lcol));
#pragma unroll
                for (int j = 0; j < 8; j++)
                    mma_tf32(acc[i][j][0], acc[i][j][1], acc[i][j][2], acc[i][j][3],
                             a0, a1, a2, a3, bf[j][0], bf[j][1]);
            }
        }
    }

    // ---- epilogue ----
    if (G1) {
#pragma unroll
        for (int j = 0; j < 8; j++) {
            int col = n0 + wn * 64 + j * 8 + 2 * c;
            float bv0 = __ldg(bias + (size_t)e * ND + col);
            float bv1 = __ldg(bias + (size_t)e * ND + col + 1);
#pragma unroll
            for (int i = 0; i < 4; i++) {
                int r0 = m0 + wm * 64 + i * 16 + g;
                if (r0 < cnt) {
                    float2 v;
                    v.x = f2tf32f(fmaxf(acc[i][j][0] + bv0, 0.f));
                    v.y = f2tf32f(fmaxf(acc[i][j][1] + bv1, 0.f));
                    *reinterpret_cast<float2*>(&g_h[(size_t)(base + r0) * ND + col]) = v;
                }
                int r1 = r0 + 8;
                if (r1 < cnt) {
                    float2 v;
                    v.x = f2tf32f(fmaxf(acc[i][j][2] + bv0, 0.f));
                    v.y = f2tf32f(fmaxf(acc[i][j][3] + bv1, 0.f));
                    *reinterpret_cast<float2*>(&g_h[(size_t)(base + r1) * ND + col]) = v;
                }
            }
        }
    } else {
        int kv = kp ? __ldg(kp) : Kq;
        if (kv <= 0) kv = Kq;
        float inv_k = 1.0f / (float)kv;
#pragma unroll
        for (int j = 0; j < 8; j++) {
            int col = n0 + wn * 64 + j * 8 + 2 * c;
            float bv0 = __ldg(bias + (size_t)e * ND + col);
            float bv1 = __ldg(bias + (size_t)e * ND + col + 1);
#pragma unroll
            for (int i = 0; i < 4; i++) {
                int r0 = m0 + wm * 64 + i * 16 + g;
                if (r0 < cnt) {
                    float* op = out + (size_t)toks[r0 - m0] * ND + col;
                    atomicAdd(op,     (acc[i][j][0] + bv0) * inv_k);
                    atomicAdd(op + 1, (acc[i][j][1] + bv1) * inv_k);
                }
                int r1 = r0 + 8;
                if (r1 < cnt) {
                    float* op = out + (size_t)toks[r1 - m0] * ND + col;
                    atomicAdd(op,     (acc[i][j][2] + bv0) * inv_k);
                    atomicAdd(op + 1, (acc[i][j][3] + bv1) * inv_k);
                }
            }
        }
    }
}

// ---------------------------------------------------------------------
// launch
// ---------------------------------------------------------------------
extern "C" void kernel_launch(void* const* d_in, const int* in_sizes, int n_in,
                              void* d_out, int out_size) {
    const float* x      = (const float*)d_in[0];
    const float* W1     = (const float*)d_in[1];
    const float* b1     = (const float*)d_in[2];
    const float* W2     = (const float*)d_in[3];
    const float* b2     = (const float*)d_in[4];
    const int*   assign = (const int*)d_in[5];
    const int*   kp     = (n_in >= 7) ? (const int*)d_in[6] : nullptr;
    float* out = (float*)d_out;

    k_zero<<<1024, 256>>>(out, out_size);
    k_detect<<<16, 256>>>(assign);
    k_build<<<16, 256>>>(assign);
    k_tiles<<<1, 32>>>();

    // x -> tf32 (RNA); weights rounded at fragment load inside GEMMs
    float* xr; cudaGetSymbolAddress((void**)&xr, g_xr);
    k_round4<<<1024, 256>>>(xr, x, NTOK * Dq / 4);

    cudaFuncSetAttribute(k_gemm_tc<Dq, Hq, true>,
                         cudaFuncAttributeMaxDynamicSharedMemorySize, SMEM_TOTAL);
    cudaFuncSetAttribute(k_gemm_tc<Hq, Dq, false>,
                         cudaFuncAttributeMaxDynamicSharedMemorySize, SMEM_TOTAL);

    // GEMM1: [rows,1024] @ [1024,4096] -> relu -> g_h (tf32-rounded)
    dim3 g1(Hq / 256, MAXTIL, 1);
    k_gemm_tc<Dq, Hq, true><<<g1, 256, SMEM_TOTAL>>>(xr, W1, b1, nullptr, nullptr);

    // GEMM2: [rows,4096] @ [4096,1024] -> scatter-add out
    dim3 g2(Dq / 256, MAXTIL, 1);
    k_gemm_tc<Hq, Dq, false><<<g2, 256, SMEM_TOTAL>>>(nullptr, W2, b2, out, kp);
}

// round 11
// speedup vs baseline: 1.3133x; 1.0781x over previous
#include <cuda_runtime.h>
#include <cuda_bf16.h>
#include <cstdint>

// Problem constants (fixed for MoELayer_20761871908984)
#define Bq     4
#define Sq     1024
#define Dq     1024
#define Hq     4096
#define Eq     8
#define Kq     2
#define NTOK   (Bq * Sq)        // 4096 tokens
#define MAXROW (NTOK * Kq)      // 8192 max (token, expert) rows
#define MAXTIL 72               // >= sum ceil(cnt_e/128) (bound 71)

// -------- device-global scratch (no runtime allocation allowed) --------
__device__ int   g_counts[Eq];
__device__ int   g_lists[Eq][NTOK];
__device__ int   g_odd_nonzero;              // !=0 -> assign int32; ==0 -> int64
__device__ int   g_tile_e[MAXTIL];
__device__ int   g_tile_m[MAXTIL];
__device__ int   g_base[Eq];
__device__ int   g_ntiles;
__device__ float g_h[(size_t)MAXROW * Hq];   // hidden activations (tf32 RNA)
__device__ float g_xr[(size_t)NTOK * Dq];    // x, tf32 RNA

// ---------------------------------------------------------------------
__global__ void k_zero(float* __restrict__ out, int n) {
    int i = blockIdx.x * blockDim.x + threadIdx.x;
    int stride = gridDim.x * blockDim.x;
    float4 z = make_float4(0.f, 0.f, 0.f, 0.f);
    int n4 = n >> 2;
    for (int j = i; j < n4; j += stride)
        reinterpret_cast<float4*>(out)[j] = z;
    for (int j = (n4 << 2) + i; j < n; j += stride)
        out[j] = 0.f;
    if (i == 0) {
        g_odd_nonzero = 0;
#pragma unroll
        for (int e = 0; e < Eq; e++) g_counts[e] = 0;
    }
}

__global__ void k_detect(const int* __restrict__ a32) {
    int i = blockIdx.x * blockDim.x + threadIdx.x;   // [0, 4096)
    int idx = 2 * i + 1;
    if (idx < NTOK * Kq) {
        if (a32[idx] != 0) atomicOr(&g_odd_nonzero, 1);
    }
}

__global__ void k_build(const int* __restrict__ a32) {
    int t = blockIdx.x * blockDim.x + threadIdx.x;
    if (t >= NTOK) return;
    int is64 = (g_odd_nonzero == 0);
    unsigned mask = 0;
#pragma unroll
    for (int j = 0; j < Kq; j++) {
        int e;
        if (is64) e = a32[(t * Kq + j) * 2];
        else      e = a32[t * Kq + j];
        mask |= 1u << (e & (Eq - 1));
    }
    while (mask) {
        int e = __ffs(mask) - 1;
        mask &= mask - 1;
        int p = atomicAdd(&g_counts[e], 1);
        g_lists[e][p] = t;
    }
}

// Build the (expert, m-tile) work table + per-expert row bases.
__global__ void k_tiles() {
    if (threadIdx.x != 0 || blockIdx.x != 0) return;
    int base = 0, nt = 0;
#pragma unroll
    for (int e = 0; e < Eq; e++) {
        int cnt = g_counts[e];
        g_base[e] = base;
        for (int m0 = 0; m0 < cnt && nt < MAXTIL; m0 += 128) {
            g_tile_e[nt] = e;
            g_tile_m[nt] = m0;
            nt++;
        }
        base += cnt;
    }
    g_ntiles = nt;
}

// ---------------------------------------------------------------------
// tf32 helpers
// ---------------------------------------------------------------------
__device__ __forceinline__ unsigned f2tf32(float f) {
    unsigned r;
    asm volatile("cvt.rna.tf32.f32 %0, %1;\n" : "=r"(r) : "f"(f));
    return r;
}
__device__ __forceinline__ float f2tf32f(float f) {
    return __uint_as_float(f2tf32(f));
}

// Prepass (x only): dst = tf32_rna(src)
__global__ void k_round4(float* __restrict__ dst, const float* __restrict__ src, int n4) {
    int i = blockIdx.x * blockDim.x + threadIdx.x;
    int stride = gridDim.x * blockDim.x;
    for (; i < n4; i += stride) {
        float4 v = reinterpret_cast<const float4*>(src)[i];
        v.x = f2tf32f(v.x); v.y = f2tf32f(v.y);
        v.z = f2tf32f(v.z); v.w = f2tf32f(v.w);
        reinterpret_cast<float4*>(dst)[i] = v;
    }
}

__device__ __forceinline__ void mma_tf32(float& d0, float& d1, float& d2, float& d3,
                                         unsigned a0, unsigned a1, unsigned a2, unsigned a3,
                                         unsigned b0, unsigned b1) {
    asm volatile(
        "mma.sync.aligned.m16n8k8.row.col.f32.tf32.tf32.f32 "
        "{%0,%1,%2,%3},{%4,%5,%6,%7},{%8,%9},{%0,%1,%2,%3};\n"
        : "+f"(d0), "+f"(d1), "+f"(d2), "+f"(d3)
        : "r"(a0), "r"(a1), "r"(a2), "r"(a3), "r"(b0), "r"(b1));
}

__device__ __forceinline__ void ldsm_x4(unsigned& r0, unsigned& r1, unsigned& r2, unsigned& r3,
                                        uint32_t addr) {
    asm volatile("ldmatrix.sync.aligned.m8n8.x4.shared.b16 {%0,%1,%2,%3}, [%4];\n"
                 : "=r"(r0), "=r"(r1), "=r"(r2), "=r"(r3) : "r"(addr));
}

__device__ __forceinline__ void cp_async16(uint32_t smem_addr, const void* gptr) {
    asm volatile("cp.async.cg.shared.global [%0], [%1], 16;\n"
                 :: "r"(smem_addr), "l"(gptr));
}
__device__ __forceinline__ void cp_commit() { asm volatile("cp.async.commit_group;\n"); }
__device__ __forceinline__ void cp_wait1()  { asm volatile("cp.async.wait_group 1;\n"); }
__device__ __forceinline__ void cp_wait0()  { asm volatile("cp.async.wait_group 0;\n"); }

// ---------------------------------------------------------------------
// Smem geometry: BK=32 per stage, 3 stages (R6 geometry).
// A: [128][ASTR=36] -> conflict-free LDSM phases.
// B: [32][BSTR=136] -> conflict-free scalar frags.
// ---------------------------------------------------------------------
#define ASTR 36
#define BSTR 136
#define NSTG 3
#define A_TILE_FLT (128 * ASTR)
#define B_TILE_FLT (32 * BSTR)
#define OFF_TOKS   0
#define OFF_A      512
#define OFF_B      (OFF_A + NSTG * A_TILE_FLT * 4)
#define SMEM_TOTAL (OFF_B + NSTG * B_TILE_FLT * 4)   // ~108 KB

// ---------------------------------------------------------------------
// tf32 grouped GEMM (mma.sync.m16n8k8).
// CTA tile 128x128, BK=32/stage, 256 threads, 8 warps 64x32.
// A: cp.async of RNA-prerounded source (g_xr / g_h).
// B: cp.async of RAW fp32 W — HMMA hardware truncates to tf32.
// No CVT instructions anywhere in the hot loop (R6 recipe).
// ---------------------------------------------------------------------
template<int KD, int ND, bool G1>
__global__ void __launch_bounds__(256, 2)
k_gemm_tc(const float* __restrict__ Ain,      // G1: g_xr ; G2: g_h
          const float* __restrict__ W,        // RAW fp32 [E][KD][ND]
          const float* __restrict__ bias,
          float* __restrict__ out,
          const int* __restrict__ kp)
{
    constexpr int NK = KD / 32;
    const int ti = blockIdx.y;
    if (ti >= g_ntiles) return;
    const int e    = g_tile_e[ti];
    const int m0   = g_tile_m[ti];
    const int cnt  = g_counts[e];
    const int base = g_base[e];
    const int n0   = blockIdx.x * 128;

    extern __shared__ __align__(16) char smem[];
    int*   toks = reinterpret_cast<int*>(smem + OFF_TOKS);
    float* As   = reinterpret_cast<float*>(smem + OFF_A);
    float* Bs   = reinterpret_cast<float*>(smem + OFF_B);

    const int tid  = threadIdx.x;
    const int lane = tid & 31;
    const int wid  = tid >> 5;
    const int wm   = wid >> 2;     // 0..1
    const int wn   = wid & 3;      // 0..3
    const int g    = lane >> 2;    // 0..7
    const int c    = lane & 3;     // 0..3

    if (tid < 128) {
        int row = m0 + tid;
        toks[tid] = (row < cnt) ? g_lists[e][row] : 0;
    }
    __syncthreads();

    // ---- A staging (cp.async): 4 chunks/thread ----
    const int aq = tid & 7;
    const float* aSrc[4];
    uint32_t aDst[4];
#pragma unroll
    for (int i = 0; i < 4; i++) {
        int m = (tid >> 3) + 32 * i;
        int row = m0 + m;
        if (G1) aSrc[i] = Ain + (size_t)toks[m] * KD + 4 * aq;
        else    aSrc[i] = g_h + (size_t)((row < cnt) ? base + row : base) * KD + 4 * aq;
        aDst[i] = (uint32_t)((m * ASTR + 4 * aq) * 4);
    }
    // ---- B staging (cp.async, raw W): 4 chunks/thread ----
    const int bnq = tid & 31;
    const int bk0 = tid >> 5;
    const float* Wp = W + (size_t)e * KD * ND;
    const uint32_t sbA = (uint32_t)__cvta_generic_to_shared(As);
    const uint32_t sbB = (uint32_t)__cvta_generic_to_shared(Bs);

    auto load_stage = [&](int kt, int buf) {
        const int k0 = kt * 32;
        const uint32_t dA = sbA + buf * A_TILE_FLT * 4;
        const uint32_t dB = sbB + buf * B_TILE_FLT * 4;
#pragma unroll
        for (int i = 0; i < 4; i++)
            cp_async16(dA + aDst[i], aSrc[i] + k0);
#pragma unroll
        for (int i = 0; i < 4; i++) {
            int k = bk0 + 8 * i;
            cp_async16(dB + (uint32_t)((k * BSTR + 4 * bnq) * 4),
                       Wp + (size_t)(k0 + k) * ND + n0 + 4 * bnq);
        }
        cp_commit();
    };

    float acc[4][4][4];
#pragma unroll
    for (int i = 0; i < 4; i++)
#pragma unroll
        for (int j = 0; j < 4; j++)
#pragma unroll
            for (int r = 0; r < 4; r++) acc[i][j][r] = 0.f;

    load_stage(0, 0);
    load_stage(1, 1);

    // ldmatrix lane addressing
    const int lrow = wm * 64 + (lane & 15);
    const int lcol = (lane >> 4) * 4;

    for (int kt = 0; kt < NK; kt++) {
        const int buf = kt % NSTG;
        if (kt + 1 < NK) cp_wait1(); else cp_wait0();
        __syncthreads();
        if (kt + 2 < NK) load_stage(kt + 2, (kt + 2) % NSTG);

        const float* Ab = As + buf * A_TILE_FLT;
        const float* Bb = Bs + buf * B_TILE_FLT;

#pragma unroll
        for (int h = 0; h < 2; h++) {        // two 16-k halves of BK=32
            const int kh = h * 16;
            // B fragments: 16 conflict-free scalar LDS (raw bits -> HW tf32)
            unsigned bf[2][4][2];
#pragma unroll
            for (int k8 = 0; k8 < 2; k8++) {
                const int kb = kh + k8 * 8;
#pragma unroll
                for (int j = 0; j < 4; j++) {
                    int nn = wn * 32 + j * 8 + g;
                    bf[k8][j][0] = __float_as_uint(Bb[(kb + c) * BSTR + nn]);
                    bf[k8][j][1] = __float_as_uint(Bb[(kb + c + 4) * BSTR + nn]);
                }
            }
            // A fragments + MMA
#pragma unroll
            for (int i = 0; i < 4; i++) {
                unsigned a0, a1, a2, a3;
                ldsm_x4(a0, a1, a2, a3,
                        (uint32_t)__cvta_generic_to_shared(
                            Ab + (lrow + i * 16) * ASTR + kh + lcol));
#pragma unroll
                for (int j = 0; j < 4; j++)
                    mma_tf32(acc[i][j][0], acc[i][j][1], acc[i][j][2], acc[i][j][3],
                             a0, a1, a2, a3, bf[0][j][0], bf[0][j][1]);
                unsigned a4, a5, a6, a7;
                ldsm_x4(a4, a5, a6, a7,
                        (uint32_t)__cvta_generic_to_shared(
                            Ab + (lrow + i * 16) * ASTR + kh + 8 + lcol));
#pragma unroll
                for (int j = 0; j < 4; j++)
                    mma_tf32(acc[i][j][0], acc[i][j][1], acc[i][j][2], acc[i][j][3],
                             a4, a5, a6, a7, bf[1][j][0], bf[1][j][1]);
            }
        }
    }

    // ---- epilogue ----
    if (G1) {
#pragma unroll
        for (int j = 0; j < 4; j++) {
            int col = n0 + wn * 32 + j * 8 + 2 * c;
            float bv0 = __ldg(bias + (size_t)e * ND + col);
            float bv1 = __ldg(bias + (size_t)e * ND + col + 1);
#pragma unroll
            for (int i = 0; i < 4; i++) {
                int r0 = m0 + wm * 64 + i * 16 + g;
                if (r0 < cnt) {
                    float2 v;
                    v.x = f2tf32f(fmaxf(acc[i][j][0] + bv0, 0.f));
                    v.y = f2tf32f(fmaxf(acc[i][j][1] + bv1, 0.f));
                    *reinterpret_cast<float2*>(&g_h[(size_t)(base + r0) * ND + col]) = v;
                }
                int r1 = r0 + 8;
                if (r1 < cnt) {
                    float2 v;
                    v.x = f2tf32f(fmaxf(acc[i][j][2] + bv0, 0.f));
                    v.y = f2tf32f(fmaxf(acc[i][j][3] + bv1, 0.f));
                    *reinterpret_cast<float2*>(&g_h[(size_t)(base + r1) * ND + col]) = v;
                }
            }
        }
    } else {
        int kv = kp ? __ldg(kp) : Kq;
        if (kv <= 0) kv = Kq;
        float inv_k = 1.0f / (float)kv;
#pragma unroll
        for (int j = 0; j < 4; j++) {
            int col = n0 + wn * 32 + j * 8 + 2 * c;
            float bv0 = __ldg(bias + (size_t)e * ND + col);
            float bv1 = __ldg(bias + (size_t)e * ND + col + 1);
#pragma unroll
            for (int i = 0; i < 4; i++) {
                int r0 = m0 + wm * 64 + i * 16 + g;
                if (r0 < cnt) {
                    float* op = out + (size_t)toks[r0 - m0] * ND + col;
                    atomicAdd(op,     (acc[i][j][0] + bv0) * inv_k);
                    atomicAdd(op + 1, (acc[i][j][1] + bv1) * inv_k);
                }
                int r1 = r0 + 8;
                if (r1 < cnt) {
                    float* op = out + (size_t)toks[r1 - m0] * ND + col;
                    atomicAdd(op,     (acc[i][j][2] + bv0) * inv_k);
                    atomicAdd(op + 1, (acc[i][j][3] + bv1) * inv_k);
                }
            }
        }
    }
}

// ---------------------------------------------------------------------
// launch
// ---------------------------------------------------------------------
extern "C" void kernel_launch(void* const* d_in, const int* in_sizes, int n_in,
                              void* d_out, int out_size) {
    const float* x      = (const float*)d_in[0];
    const float* W1     = (const float*)d_in[1];
    const float* b1     = (const float*)d_in[2];
    const float* W2     = (const float*)d_in[3];
    const float* b2     = (const float*)d_in[4];
    const int*   assign = (const int*)d_in[5];
    const int*   kp     = (n_in >= 7) ? (const int*)d_in[6] : nullptr;
    float* out = (float*)d_out;

    k_zero<<<1024, 256>>>(out, out_size);
    k_detect<<<16, 256>>>(assign);
    k_build<<<16, 256>>>(assign);
    k_tiles<<<1, 32>>>();

    // x -> tf32 RNA; weights fed raw (HW truncation in HMMA)
    float* xr; cudaGetSymbolAddress((void**)&xr, g_xr);
    k_round4<<<1024, 256>>>(xr, x, NTOK * Dq / 4);

    cudaFuncSetAttribute(k_gemm_tc<Dq, Hq, true>,
                         cudaFuncAttributeMaxDynamicSharedMemorySize, SMEM_TOTAL);
    cudaFuncSetAttribute(k_gemm_tc<Hq, Dq, false>,
                         cudaFuncAttributeMaxDynamicSharedMemorySize, SMEM_TOTAL);

    // GEMM1: [rows,1024] @ [1024,4096] -> relu -> g_h (tf32 RNA)
    dim3 g1(Hq / 128, MAXTIL, 1);
    k_gemm_tc<Dq, Hq, true><<<g1, 256, SMEM_TOTAL>>>(xr, W1, b1, nullptr, nullptr);

    // GEMM2: [rows,4096] @ [4096,1024] -> scatter-add out
    dim3 g2(Dq / 128, MAXTIL, 1);
    k_gemm_tc<Hq, Dq, false><<<g2, 256, SMEM_TOTAL>>>(nullptr, W2, b2, out, kp);
}

// round 12
// speedup vs baseline: 1.8085x; 1.3771x over previous
#include <cuda_runtime.h>
#include <cuda_fp16.h>
#include <cstdint>

// Problem constants (fixed for MoELayer_20761871908984)
#define Bq     4
#define Sq     1024
#define Dq     1024
#define Hq     4096
#define Eq     8
#define Kq     2
#define NTOK   (Bq * Sq)        // 4096 tokens
#define MAXROW (NTOK * Kq)      // 8192 max (token, expert) rows
#define MAXTIL 72               // >= sum ceil(cnt_e/128) (bound 71)

// -------- device-global scratch (no runtime allocation allowed) --------
__device__ int    g_counts[Eq];
__device__ int    g_lists[Eq][NTOK];
__device__ int    g_odd_nonzero;             // !=0 -> assign int32; ==0 -> int64
__device__ int    g_tile_e[MAXTIL];
__device__ int    g_tile_m[MAXTIL];
__device__ int    g_base[Eq];
__device__ int    g_ntiles;
__device__ __half g_xh [(size_t)NTOK * Dq];       //   8 MB x  (fp16 RNE)
__device__ __half g_hh [(size_t)MAXROW * Hq];     //  64 MB hidden (fp16 RNE)
__device__ __half g_w1h[(size_t)Eq * Dq * Hq];    //  64 MB W1 (fp16 RNE)
__device__ __half g_w2h[(size_t)Eq * Hq * Dq];    //  64 MB W2 (fp16 RNE)

// ---------------------------------------------------------------------
__global__ void k_zero(float* __restrict__ out, int n) {
    int i = blockIdx.x * blockDim.x + threadIdx.x;
    int stride = gridDim.x * blockDim.x;
    float4 z = make_float4(0.f, 0.f, 0.f, 0.f);
    int n4 = n >> 2;
    for (int j = i; j < n4; j += stride)
        reinterpret_cast<float4*>(out)[j] = z;
    for (int j = (n4 << 2) + i; j < n; j += stride)
        out[j] = 0.f;
    if (i == 0) {
        g_odd_nonzero = 0;
#pragma unroll
        for (int e = 0; e < Eq; e++) g_counts[e] = 0;
    }
}

__global__ void k_detect(const int* __restrict__ a32) {
    int i = blockIdx.x * blockDim.x + threadIdx.x;   // [0, 4096)
    int idx = 2 * i + 1;
    if (idx < NTOK * Kq) {
        if (a32[idx] != 0) atomicOr(&g_odd_nonzero, 1);
    }
}

__global__ void k_build(const int* __restrict__ a32) {
    int t = blockIdx.x * blockDim.x + threadIdx.x;
    if (t >= NTOK) return;
    int is64 = (g_odd_nonzero == 0);
    unsigned mask = 0;
#pragma unroll
    for (int j = 0; j < Kq; j++) {
        int e;
        if (is64) e = a32[(t * Kq + j) * 2];
        else      e = a32[t * Kq + j];
        mask |= 1u << (e & (Eq - 1));
    }
    while (mask) {
        int e = __ffs(mask) - 1;
        mask &= mask - 1;
        int p = atomicAdd(&g_counts[e], 1);
        g_lists[e][p] = t;
    }
}

// Build the (expert, m-tile) work table + per-expert row bases.
__global__ void k_tiles() {
    if (threadIdx.x != 0 || blockIdx.x != 0) return;
    int base = 0, nt = 0;
#pragma unroll
    for (int e = 0; e < Eq; e++) {
        int cnt = g_counts[e];
        g_base[e] = base;
        for (int m0 = 0; m0 < cnt && nt < MAXTIL; m0 += 128) {
            g_tile_e[nt] = e;
            g_tile_m[nt] = m0;
            nt++;
        }
        base += cnt;
    }
    g_ntiles = nt;
}

// Prepass: fp32 -> fp16 (RNE), vectorized grid-stride.
__global__ void k_tohalf(__half* __restrict__ dst, const float* __restrict__ src, int n4) {
    int i = blockIdx.x * blockDim.x + threadIdx.x;
    int stride = gridDim.x * blockDim.x;
    for (; i < n4; i += stride) {
        float4 v = reinterpret_cast<const float4*>(src)[i];
        __half2 h0 = __floats2half2_rn(v.x, v.y);
        __half2 h1 = __floats2half2_rn(v.z, v.w);
        uint2 o;
        o.x = reinterpret_cast<unsigned&>(h0);
        o.y = reinterpret_cast<unsigned&>(h1);
        reinterpret_cast<uint2*>(dst)[i] = o;
    }
}

// ---------------------------------------------------------------------
// fp16 MMA + ldmatrix + cp.async helpers
// ---------------------------------------------------------------------
__device__ __forceinline__ void mma_f16(float& d0, float& d1, float& d2, float& d3,
                                        unsigned a0, unsigned a1, unsigned a2, unsigned a3,
                                        unsigned b0, unsigned b1) {
    asm volatile(
        "mma.sync.aligned.m16n8k16.row.col.f32.f16.f16.f32 "
        "{%0,%1,%2,%3},{%4,%5,%6,%7},{%8,%9},{%0,%1,%2,%3};\n"
        : "+f"(d0), "+f"(d1), "+f"(d2), "+f"(d3)
        : "r"(a0), "r"(a1), "r"(a2), "r"(a3), "r"(b0), "r"(b1));
}

__device__ __forceinline__ void ldsm_x4(unsigned& r0, unsigned& r1, unsigned& r2, unsigned& r3,
                                        uint32_t addr) {
    asm volatile("ldmatrix.sync.aligned.m8n8.x4.shared.b16 {%0,%1,%2,%3}, [%4];\n"
                 : "=r"(r0), "=r"(r1), "=r"(r2), "=r"(r3) : "r"(addr));
}
__device__ __forceinline__ void ldsm_x4_t(unsigned& r0, unsigned& r1, unsigned& r2, unsigned& r3,
                                          uint32_t addr) {
    asm volatile("ldmatrix.sync.aligned.m8n8.x4.trans.shared.b16 {%0,%1,%2,%3}, [%4];\n"
                 : "=r"(r0), "=r"(r1), "=r"(r2), "=r"(r3) : "r"(addr));
}

__device__ __forceinline__ void cp_async16(uint32_t smem_addr, const void* gptr) {
    asm volatile("cp.async.cg.shared.global [%0], [%1], 16;\n"
                 :: "r"(smem_addr), "l"(gptr));
}
__device__ __forceinline__ void cp_commit() { asm volatile("cp.async.commit_group;\n"); }
__device__ __forceinline__ void cp_wait1()  { asm volatile("cp.async.wait_group 1;\n"); }
__device__ __forceinline__ void cp_wait0()  { asm volatile("cp.async.wait_group 0;\n"); }

// ---------------------------------------------------------------------
// Smem geometry (halves): BK=32 per stage, 3 stages.
// A: [128][ASTR=40] halves (80B rows) -> 8-row LDSM phase = 32-bank partition.
// B: [32][BSTR=136] halves (272B rows) -> trans-LDSM phase = partition.
// ---------------------------------------------------------------------
#define ASTR 40
#define BSTR 136
#define NSTG 3
#define A_TILE_B (128 * ASTR * 2)          // 10240 B
#define B_TILE_B (32 * BSTR * 2)           // 8704 B
#define OFF_TOKS 0
#define OFF_A    512
#define OFF_B    (OFF_A + NSTG * A_TILE_B)           // 31232
#define SMEM_TOTAL (OFF_B + NSTG * B_TILE_B)         // 57344 (56 KB)

// ---------------------------------------------------------------------
// fp16 grouped GEMM (mma.sync.m16n8k16), 2x tf32 rate.
// CTA tile 128x128, BK=32/stage, 256 threads, 8 warps 64x32.
// A: [m][k] halves via cp.async; frags via ldmatrix.x4.
// B: [k][n] halves via cp.async; frags via ldmatrix.x4.trans.
// ---------------------------------------------------------------------
template<int KD, int ND, bool G1>
__global__ void __launch_bounds__(256, 2)
k_gemm_f16(const __half* __restrict__ Ain,    // G1: g_xh ; G2: g_hh
           const __half* __restrict__ W,      // fp16 [E][KD][ND]
           const float* __restrict__ bias,
           float* __restrict__ out,
           const int* __restrict__ kp)
{
    constexpr int NK = KD / 32;
    const int ti = blockIdx.y;
    if (ti >= g_ntiles) return;
    const int e    = g_tile_e[ti];
    const int m0   = g_tile_m[ti];
    const int cnt  = g_counts[e];
    const int base = g_base[e];
    const int n0   = blockIdx.x * 128;

    extern __shared__ __align__(16) char smem[];
    int* toks = reinterpret_cast<int*>(smem + OFF_TOKS);

    const int tid  = threadIdx.x;
    const int lane = tid & 31;
    const int wid  = tid >> 5;
    const int wm   = wid >> 2;     // 0..1  (64-row band)
    const int wn   = wid & 3;      // 0..3  (32-col band)
    const int g    = lane >> 2;    // 0..7
    const int c    = lane & 3;     // 0..3

    if (tid < 128) {
        int row = m0 + tid;
        toks[tid] = (row < cnt) ? g_lists[e][row] : 0;
    }
    __syncthreads();

    const uint32_t sb  = (uint32_t)__cvta_generic_to_shared(smem);
    const uint32_t sbA = sb + OFF_A;
    const uint32_t sbB = sb + OFF_B;

    // ---- A staging: 2 chunks/thread. m = tid>>2 + 64i, q = tid&3 ----
    const int aq = tid & 3;
    const __half* aSrc[2];
    uint32_t aDst[2];
#pragma unroll
    for (int i = 0; i < 2; i++) {
        int m = (tid >> 2) + 64 * i;
        int row = m0 + m;
        if (G1) aSrc[i] = Ain + (size_t)toks[m] * KD + 8 * aq;
        else    aSrc[i] = g_hh + (size_t)((row < cnt) ? base + row : base) * KD + 8 * aq;
        aDst[i] = (uint32_t)(m * (ASTR * 2) + aq * 16);
    }
    // ---- B staging: 2 chunks/thread. k = tid>>4 + 16i, nq = tid&15 ----
    const int bnq = tid & 15;
    const int bk0 = tid >> 4;
    const __half* Wp = W + (size_t)e * KD * ND;

    auto load_stage = [&](int kt, int buf) {
        const int k0 = kt * 32;
        const uint32_t dA = sbA + buf * A_TILE_B;
        const uint32_t dB = sbB + buf * B_TILE_B;
#pragma unroll
        for (int i = 0; i < 2; i++)
            cp_async16(dA + aDst[i], aSrc[i] + k0);
#pragma unroll
        for (int i = 0; i < 2; i++) {
            int k = bk0 + 16 * i;
            cp_async16(dB + (uint32_t)(k * (BSTR * 2) + bnq * 16),
                       Wp + (size_t)(k0 + k) * ND + n0 + 8 * bnq);
        }
        cp_commit();
    };

    float acc[4][4][4];
#pragma unroll
    for (int i = 0; i < 4; i++)
#pragma unroll
        for (int j = 0; j < 4; j++)
#pragma unroll
            for (int r = 0; r < 4; r++) acc[i][j][r] = 0.f;

    load_stage(0, 0);
    load_stage(1, 1);

    // A ldmatrix lane addressing: rows lrow (+16i), k-byte = h*32 + (lane>>4)*16
    const int lrow  = wm * 64 + (lane & 15);
    const int lakb  = (lane >> 4) * 16;             // bytes within 16-k (32B) band
    // B trans ldmatrix lane addressing: k-row = (lane&7) + ((lane>>4)<<3),
    // n-byte = ((lane>>3)&1)*16 + (wn*32 + t*16)*2
    const int bkrow = (lane & 7) + ((lane >> 4) << 3);
    const int bnb0  = ((lane >> 3) & 1) * 16 + (wn * 32) * 2;

    for (int kt = 0; kt < NK; kt++) {
        const int buf = kt % NSTG;
        if (kt + 1 < NK) cp_wait1(); else cp_wait0();
        __syncthreads();
        if (kt + 2 < NK) load_stage(kt + 2, (kt + 2) % NSTG);

        const uint32_t Ab = sbA + buf * A_TILE_B;
        const uint32_t Bb = sbB + buf * B_TILE_B;

#pragma unroll
        for (int h = 0; h < 2; h++) {                 // two 16-k steps of BK=32
            // B fragments: 2x ldmatrix.x4.trans -> b0/b1 for 4 n-tiles of 8
            unsigned b0[4], b1[4];
#pragma unroll
            for (int t = 0; t < 2; t++) {
                unsigned r0, r1, r2, r3;
                uint32_t baddr = Bb + (uint32_t)((h * 16 + bkrow) * (BSTR * 2)
                                                 + bnb0 + t * 32);
                ldsm_x4_t(r0, r1, r2, r3, baddr);
                b0[2 * t]     = r0;  b0[2 * t + 1] = r1;
                b1[2 * t]     = r2;  b1[2 * t + 1] = r3;
            }
            // A fragments + MMA
#pragma unroll
            for (int i = 0; i < 4; i++) {
                unsigned a0, a1, a2, a3;
                uint32_t aaddr = Ab + (uint32_t)((lrow + i * 16) * (ASTR * 2)
                                                 + h * 32 + lakb);
                ldsm_x4(a0, a1, a2, a3, aaddr);
#pragma unroll
                for (int j = 0; j < 4; j++)
                    mma_f16(acc[i][j][0], acc[i][j][1], acc[i][j][2], acc[i][j][3],
                            a0, a1, a2, a3, b0[j], b1[j]);
            }
        }
    }

    // ---- epilogue ----
    if (G1) {
        // relu(acc + b1) -> fp16 RNE -> g_hh
#pragma unroll
        for (int j = 0; j < 4; j++) {
            int col = n0 + wn * 32 + j * 8 + 2 * c;
            float bv0 = __ldg(bias + (size_t)e * ND + col);
            float bv1 = __ldg(bias + (size_t)e * ND + col + 1);
#pragma unroll
            for (int i = 0; i < 4; i++) {
                int r0 = m0 + wm * 64 + i * 16 + g;
                if (r0 < cnt) {
                    __half2 v = __floats2half2_rn(fmaxf(acc[i][j][0] + bv0, 0.f),
                                                  fmaxf(acc[i][j][1] + bv1, 0.f));
                    *reinterpret_cast<__half2*>(&g_hh[(size_t)(base + r0) * ND + col]) = v;
                }
                int r1 = r0 + 8;
                if (r1 < cnt) {
                    __half2 v = __floats2half2_rn(fmaxf(acc[i][j][2] + bv0, 0.f),
                                                  fmaxf(acc[i][j][3] + bv1, 0.f));
                    *reinterpret_cast<__half2*>(&g_hh[(size_t)(base + r1) * ND + col]) = v;
                }
            }
        }
    } else {
        int kv = kp ? __ldg(kp) : Kq;
        if (kv <= 0) kv = Kq;
        float inv_k = 1.0f / (float)kv;
#pragma unroll
        for (int j = 0; j < 4; j++) {
            int col = n0 + wn * 32 + j * 8 + 2 * c;
            float bv0 = __ldg(bias + (size_t)e * ND + col);
            float bv1 = __ldg(bias + (size_t)e * ND + col + 1);
#pragma unroll
            for (int i = 0; i < 4; i++) {
                int r0 = m0 + wm * 64 + i * 16 + g;
                if (r0 < cnt) {
                    float* op = out + (size_t)toks[r0 - m0] * ND + col;
                    atomicAdd(op,     (acc[i][j][0] + bv0) * inv_k);
                    atomicAdd(op + 1, (acc[i][j][1] + bv1) * inv_k);
                }
                int r1 = r0 + 8;
                if (r1 < cnt) {
                    float* op = out + (size_t)toks[r1 - m0] * ND + col;
                    atomicAdd(op,     (acc[i][j][2] + bv0) * inv_k);
                    atomicAdd(op + 1, (acc[i][j][3] + bv1) * inv_k);
                }
            }
        }
    }
}

// ---------------------------------------------------------------------
// launch
// ---------------------------------------------------------------------
extern "C" void kernel_launch(void* const* d_in, const int* in_sizes, int n_in,
                              void* d_out, int out_size) {
    const float* x      = (const float*)d_in[0];
    const float* W1     = (const float*)d_in[1];
    const float* b1     = (const float*)d_in[2];
    const float* W2     = (const float*)d_in[3];
    const float* b2     = (const float*)d_in[4];
    const int*   assign = (const int*)d_in[5];
    const int*   kp     = (n_in >= 7) ? (const int*)d_in[6] : nullptr;
    float* out = (float*)d_out;

    k_zero<<<1024, 256>>>(out, out_size);
    k_detect<<<16, 256>>>(assign);
    k_build<<<16, 256>>>(assign);
    k_tiles<<<1, 32>>>();

    // fp16 conversion prepass (RNE): x, W1, W2
    __half *xh, *w1h, *w2h;
    cudaGetSymbolAddress((void**)&xh,  g_xh);
    cudaGetSymbolAddress((void**)&w1h, g_w1h);
    cudaGetSymbolAddress((void**)&w2h, g_w2h);
    k_tohalf<<<1024, 256>>>(xh,  x,  NTOK * Dq / 4);
    k_tohalf<<<4096, 256>>>(w1h, W1, Eq * Dq * Hq / 4);
    k_tohalf<<<4096, 256>>>(w2h, W2, Eq * Hq * Dq / 4);

    cudaFuncSetAttribute(k_gemm_f16<Dq, Hq, true>,
                         cudaFuncAttributeMaxDynamicSharedMemorySize, SMEM_TOTAL);
    cudaFuncSetAttribute(k_gemm_f16<Hq, Dq, false>,
                         cudaFuncAttributeMaxDynamicSharedMemorySize, SMEM_TOTAL);

    // GEMM1: [rows,1024] @ [1024,4096] -> relu -> g_hh (fp16)
    dim3 g1(Hq / 128, MAXTIL, 1);
    k_gemm_f16<Dq, Hq, true><<<g1, 256, SMEM_TOTAL>>>(xh, w1h, b1, nullptr, nullptr);

    // GEMM2: [rows,4096] @ [4096,1024] -> scatter-add out
    dim3 g2(Dq / 128, MAXTIL, 1);
    k_gemm_f16<Hq, Dq, false><<<g2, 256, SMEM_TOTAL>>>(nullptr, w2h, b2, out, kp);
}

// round 13
// speedup vs baseline: 1.8399x; 1.0173x over previous
#include <cuda_runtime.h>
#include <cuda_fp16.h>
#include <cstdint>

// Problem constants (fixed for MoELayer_20761871908984)
#define Bq     4
#define Sq     1024
#define Dq     1024
#define Hq     4096
#define Eq     8
#define Kq     2
#define NTOK   (Bq * Sq)        // 4096 tokens
#define MAXROW (NTOK * Kq)      // 8192 max (token, expert) rows
#define MAXTIL 72               // >= sum ceil(cnt_e/128) (bound 71)

// -------- device-global scratch (no runtime allocation allowed) --------
__device__ int    g_counts[Eq];
__device__ int    g_lists[Eq][NTOK];
__device__ int    g_odd_nonzero;             // !=0 -> assign int32; ==0 -> int64
__device__ int    g_tile_e[MAXTIL];
__device__ int    g_tile_m[MAXTIL];
__device__ int    g_base[Eq];
__device__ int    g_ntiles;
__device__ __half g_xh [(size_t)NTOK * Dq];       //   8 MB x  (fp16 RNE)
__device__ __half g_hh [(size_t)MAXROW * Hq];     //  64 MB hidden (fp16 RNE)
__device__ __half g_w1h[(size_t)Eq * Dq * Hq];    //  64 MB W1 (fp16 RNE)
__device__ __half g_w2h[(size_t)Eq * Hq * Dq];    //  64 MB W2 (fp16 RNE)

// ---------------------------------------------------------------------
__global__ void k_zero(float* __restrict__ out, int n) {
    int i = blockIdx.x * blockDim.x + threadIdx.x;
    int stride = gridDim.x * blockDim.x;
    float4 z = make_float4(0.f, 0.f, 0.f, 0.f);
    int n4 = n >> 2;
    for (int j = i; j < n4; j += stride)
        reinterpret_cast<float4*>(out)[j] = z;
    for (int j = (n4 << 2) + i; j < n; j += stride)
        out[j] = 0.f;
    if (i == 0) {
        g_odd_nonzero = 0;
#pragma unroll
        for (int e = 0; e < Eq; e++) g_counts[e] = 0;
    }
}

__global__ void k_detect(const int* __restrict__ a32) {
    int i = blockIdx.x * blockDim.x + threadIdx.x;   // [0, 4096)
    int idx = 2 * i + 1;
    if (idx < NTOK * Kq) {
        if (a32[idx] != 0) atomicOr(&g_odd_nonzero, 1);
    }
}

__global__ void k_build(const int* __restrict__ a32) {
    int t = blockIdx.x * blockDim.x + threadIdx.x;
    if (t >= NTOK) return;
    int is64 = (g_odd_nonzero == 0);
    unsigned mask = 0;
#pragma unroll
    for (int j = 0; j < Kq; j++) {
        int e;
        if (is64) e = a32[(t * Kq + j) * 2];
        else      e = a32[t * Kq + j];
        mask |= 1u << (e & (Eq - 1));
    }
    while (mask) {
        int e = __ffs(mask) - 1;
        mask &= mask - 1;
        int p = atomicAdd(&g_counts[e], 1);
        g_lists[e][p] = t;
    }
}

// Build the (expert, m-tile) work table + per-expert row bases.
__global__ void k_tiles() {
    if (threadIdx.x != 0 || blockIdx.x != 0) return;
    int base = 0, nt = 0;
#pragma unroll
    for (int e = 0; e < Eq; e++) {
        int cnt = g_counts[e];
        g_base[e] = base;
        for (int m0 = 0; m0 < cnt && nt < MAXTIL; m0 += 128) {
            g_tile_e[nt] = e;
            g_tile_m[nt] = m0;
            nt++;
        }
        base += cnt;
    }
    g_ntiles = nt;
}

// Prepass: fp32 -> fp16 (RNE), 8 elems/iter, 16B stores.
__global__ void k_tohalf8(__half* __restrict__ dst, const float* __restrict__ src, int n8) {
    int i = blockIdx.x * blockDim.x + threadIdx.x;
    int stride = gridDim.x * blockDim.x;
    for (; i < n8; i += stride) {
        float4 a = reinterpret_cast<const float4*>(src)[2 * i];
        float4 b = reinterpret_cast<const float4*>(src)[2 * i + 1];
        __half2 h0 = __floats2half2_rn(a.x, a.y);
        __half2 h1 = __floats2half2_rn(a.z, a.w);
        __half2 h2 = __floats2half2_rn(b.x, b.y);
        __half2 h3 = __floats2half2_rn(b.z, b.w);
        uint4 o;
        o.x = reinterpret_cast<unsigned&>(h0);
        o.y = reinterpret_cast<unsigned&>(h1);
        o.z = reinterpret_cast<unsigned&>(h2);
        o.w = reinterpret_cast<unsigned&>(h3);
        reinterpret_cast<uint4*>(dst)[i] = o;
    }
}

// ---------------------------------------------------------------------
// fp16 MMA + ldmatrix + cp.async helpers
// ---------------------------------------------------------------------
__device__ __forceinline__ void mma_f16(float& d0, float& d1, float& d2, float& d3,
                                        unsigned a0, unsigned a1, unsigned a2, unsigned a3,
                                        unsigned b0, unsigned b1) {
    asm volatile(
        "mma.sync.aligned.m16n8k16.row.col.f32.f16.f16.f32 "
        "{%0,%1,%2,%3},{%4,%5,%6,%7},{%8,%9},{%0,%1,%2,%3};\n"
        : "+f"(d0), "+f"(d1), "+f"(d2), "+f"(d3)
        : "r"(a0), "r"(a1), "r"(a2), "r"(a3), "r"(b0), "r"(b1));
}

__device__ __forceinline__ void ldsm_x4(unsigned& r0, unsigned& r1, unsigned& r2, unsigned& r3,
                                        uint32_t addr) {
    asm volatile("ldmatrix.sync.aligned.m8n8.x4.shared.b16 {%0,%1,%2,%3}, [%4];\n"
                 : "=r"(r0), "=r"(r1), "=r"(r2), "=r"(r3) : "r"(addr));
}
__device__ __forceinline__ void ldsm_x4_t(unsigned& r0, unsigned& r1, unsigned& r2, unsigned& r3,
                                          uint32_t addr) {
    asm volatile("ldmatrix.sync.aligned.m8n8.x4.trans.shared.b16 {%0,%1,%2,%3}, [%4];\n"
                 : "=r"(r0), "=r"(r1), "=r"(r2), "=r"(r3) : "r"(addr));
}

__device__ __forceinline__ void cp_async16(uint32_t smem_addr, const void* gptr) {
    asm volatile("cp.async.cg.shared.global [%0], [%1], 16;\n"
                 :: "r"(smem_addr), "l"(gptr));
}
__device__ __forceinline__ void cp_commit() { asm volatile("cp.async.commit_group;\n"); }
__device__ __forceinline__ void cp_wait1()  { asm volatile("cp.async.wait_group 1;\n"); }
__device__ __forceinline__ void cp_wait0()  { asm volatile("cp.async.wait_group 0;\n"); }

// ---------------------------------------------------------------------
// Smem geometry (halves): BK=32 per stage, 3 stages.
// A: [128][ASTR=40] halves -> 8-row LDSM phase = 32-bank partition.
// B: [32][BSTR=136] halves -> trans-LDSM phase = partition.
// ---------------------------------------------------------------------
#define ASTR 40
#define BSTR 136
#define NSTG 3
#define A_TILE_B (128 * ASTR * 2)          // 10240 B
#define B_TILE_B (32 * BSTR * 2)           // 8704 B
#define OFF_TOKS 0
#define OFF_A    512
#define OFF_B    (OFF_A + NSTG * A_TILE_B)           // 31232
#define SMEM_TOTAL (OFF_B + NSTG * B_TILE_B)         // 57344 (56 KB)

// ---------------------------------------------------------------------
// fp16 grouped GEMM (mma.sync.m16n8k16).
// CTA tile 128x128, BK=32/stage, 256 threads, 8 warps 64x32.
// Optional fused tail: grid-stride fp32->fp16 conversion of cvt_src
// (W2) overlapped with GEMM1's tensor-bound execution.
// ---------------------------------------------------------------------
template<int KD, int ND, bool G1>
__global__ void __launch_bounds__(256, 2)
k_gemm_f16(const __half* __restrict__ Ain,    // G1: g_xh ; G2: g_hh
           const __half* __restrict__ W,      // fp16 [E][KD][ND]
           const float* __restrict__ bias,
           float* __restrict__ out,
           const int* __restrict__ kp,
           const float* __restrict__ cvt_src, // fused conversion (or null)
           __half* __restrict__ cvt_dst,
           int cvt_n8)
{
    constexpr int NK = KD / 32;
    const int ti = blockIdx.y;

    if (ti < g_ntiles) {
        const int e    = g_tile_e[ti];
        const int m0   = g_tile_m[ti];
        const int cnt  = g_counts[e];
        const int base = g_base[e];
        const int n0   = blockIdx.x * 128;

        extern __shared__ __align__(16) char smem[];
        int* toks = reinterpret_cast<int*>(smem + OFF_TOKS);

        const int tid  = threadIdx.x;
        const int lane = tid & 31;
        const int wid  = tid >> 5;
        const int wm   = wid >> 2;     // 0..1  (64-row band)
        const int wn   = wid & 3;      // 0..3  (32-col band)
        const int g    = lane >> 2;    // 0..7
        const int c    = lane & 3;     // 0..3

        if (tid < 128) {
            int row = m0 + tid;
            toks[tid] = (row < cnt) ? g_lists[e][row] : 0;
        }
        __syncthreads();

        const uint32_t sb  = (uint32_t)__cvta_generic_to_shared(smem);
        const uint32_t sbA = sb + OFF_A;
        const uint32_t sbB = sb + OFF_B;

        // ---- A staging: 2 chunks/thread. m = tid>>2 + 64i, q = tid&3 ----
        const int aq = tid & 3;
        const __half* aSrc[2];
        uint32_t aDst[2];
#pragma unroll
        for (int i = 0; i < 2; i++) {
            int m = (tid >> 2) + 64 * i;
            int row = m0 + m;
            if (G1) aSrc[i] = Ain + (size_t)toks[m] * KD + 8 * aq;
            else    aSrc[i] = g_hh + (size_t)((row < cnt) ? base + row : base) * KD + 8 * aq;
            aDst[i] = (uint32_t)(m * (ASTR * 2) + aq * 16);
        }
        // ---- B staging: 2 chunks/thread. k = tid>>4 + 16i, nq = tid&15 ----
        const int bnq = tid & 15;
        const int bk0 = tid >> 4;
        const __half* Wp = W + (size_t)e * KD * ND;

        auto load_stage = [&](int kt, int buf) {
            const int k0 = kt * 32;
            const uint32_t dA = sbA + buf * A_TILE_B;
            const uint32_t dB = sbB + buf * B_TILE_B;
#pragma unroll
            for (int i = 0; i < 2; i++)
                cp_async16(dA + aDst[i], aSrc[i] + k0);
#pragma unroll
            for (int i = 0; i < 2; i++) {
                int k = bk0 + 16 * i;
                cp_async16(dB + (uint32_t)(k * (BSTR * 2) + bnq * 16),
                           Wp + (size_t)(k0 + k) * ND + n0 + 8 * bnq);
            }
            cp_commit();
        };

        float acc[4][4][4];
#pragma unroll
        for (int i = 0; i < 4; i++)
#pragma unroll
            for (int j = 0; j < 4; j++)
#pragma unroll
                for (int r = 0; r < 4; r++) acc[i][j][r] = 0.f;

        load_stage(0, 0);
        load_stage(1, 1);

        const int lrow  = wm * 64 + (lane & 15);
        const int lakb  = (lane >> 4) * 16;
        const int bkrow = (lane & 7) + ((lane >> 4) << 3);
        const int bnb0  = ((lane >> 3) & 1) * 16 + (wn * 32) * 2;

        for (int kt = 0; kt < NK; kt++) {
            const int buf = kt % NSTG;
            if (kt + 1 < NK) cp_wait1(); else cp_wait0();
            __syncthreads();
            if (kt + 2 < NK) load_stage(kt + 2, (kt + 2) % NSTG);

            const uint32_t Ab = sbA + buf * A_TILE_B;
            const uint32_t Bb = sbB + buf * B_TILE_B;

#pragma unroll
            for (int h = 0; h < 2; h++) {
                unsigned b0[4], b1[4];
#pragma unroll
                for (int t = 0; t < 2; t++) {
                    unsigned r0, r1, r2, r3;
                    uint32_t baddr = Bb + (uint32_t)((h * 16 + bkrow) * (BSTR * 2)
                                                     + bnb0 + t * 32);
                    ldsm_x4_t(r0, r1, r2, r3, baddr);
                    b0[2 * t]     = r0;  b0[2 * t + 1] = r1;
                    b1[2 * t]     = r2;  b1[2 * t + 1] = r3;
                }
#pragma unroll
                for (int i = 0; i < 4; i++) {
                    unsigned a0, a1, a2, a3;
                    uint32_t aaddr = Ab + (uint32_t)((lrow + i * 16) * (ASTR * 2)
                                                     + h * 32 + lakb);
                    ldsm_x4(a0, a1, a2, a3, aaddr);
#pragma unroll
                    for (int j = 0; j < 4; j++)
                        mma_f16(acc[i][j][0], acc[i][j][1], acc[i][j][2], acc[i][j][3],
                                a0, a1, a2, a3, b0[j], b1[j]);
                }
            }
        }

        // ---- epilogue ----
        if (G1) {
#pragma unroll
            for (int j = 0; j < 4; j++) {
                int col = n0 + wn * 32 + j * 8 + 2 * c;
                float bv0 = __ldg(bias + (size_t)e * ND + col);
                float bv1 = __ldg(bias + (size_t)e * ND + col + 1);
#pragma unroll
                for (int i = 0; i < 4; i++) {
                    int r0 = m0 + wm * 64 + i * 16 + g;
                    if (r0 < cnt) {
                        __half2 v = __floats2half2_rn(fmaxf(acc[i][j][0] + bv0, 0.f),
                                                      fmaxf(acc[i][j][1] + bv1, 0.f));
                        *reinterpret_cast<__half2*>(&g_hh[(size_t)(base + r0) * ND + col]) = v;
                    }
                    int r1 = r0 + 8;
                    if (r1 < cnt) {
                        __half2 v = __floats2half2_rn(fmaxf(acc[i][j][2] + bv0, 0.f),
                                                      fmaxf(acc[i][j][3] + bv1, 0.f));
                        *reinterpret_cast<__half2*>(&g_hh[(size_t)(base + r1) * ND + col]) = v;
                    }
                }
            }
        } else {
            int kv = kp ? __ldg(kp) : Kq;
            if (kv <= 0) kv = Kq;
            float inv_k = 1.0f / (float)kv;
#pragma unroll
            for (int j = 0; j < 4; j++) {
                int col = n0 + wn * 32 + j * 8 + 2 * c;
                float bv0 = __ldg(bias + (size_t)e * ND + col);
                float bv1 = __ldg(bias + (size_t)e * ND + col + 1);
#pragma unroll
                for (int i = 0; i < 4; i++) {
                    int r0 = m0 + wm * 64 + i * 16 + g;
                    if (r0 < cnt) {
                        float* op = out + (size_t)toks[r0 - m0] * ND + col;
                        atomicAdd(op,     (acc[i][j][0] + bv0) * inv_k);
                        atomicAdd(op + 1, (acc[i][j][1] + bv1) * inv_k);
                    }
                    int r1 = r0 + 8;
                    if (r1 < cnt) {
                        float* op = out + (size_t)toks[r1 - m0] * ND + col;
                        atomicAdd(op,     (acc[i][j][2] + bv0) * inv_k);
                        atomicAdd(op + 1, (acc[i][j][3] + bv1) * inv_k);
                    }
                }
            }
        }
    }

    // ---- fused conversion tail (all CTAs, incl. early-return ones) ----
    if (cvt_src) {
        int gtid = (blockIdx.y * gridDim.x + blockIdx.x) * blockDim.x + threadIdx.x;
        int gstride = gridDim.x * gridDim.y * blockDim.x;
        for (int i = gtid; i < cvt_n8; i += gstride) {
            float4 a = reinterpret_cast<const float4*>(cvt_src)[2 * i];
            float4 b = reinterpret_cast<const float4*>(cvt_src)[2 * i + 1];
            __half2 h0 = __floats2half2_rn(a.x, a.y);
            __half2 h1 = __floats2half2_rn(a.z, a.w);
            __half2 h2 = __floats2half2_rn(b.x, b.y);
            __half2 h3 = __floats2half2_rn(b.z, b.w);
            uint4 o;
            o.x = reinterpret_cast<unsigned&>(h0);
            o.y = reinterpret_cast<unsigned&>(h1);
            o.z = reinterpret_cast<unsigned&>(h2);
            o.w = reinterpret_cast<unsigned&>(h3);
            reinterpret_cast<uint4*>(cvt_dst)[i] = o;
        }
    }
}

// ---------------------------------------------------------------------
// launch
// ---------------------------------------------------------------------
extern "C" void kernel_launch(void* const* d_in, const int* in_sizes, int n_in,
                              void* d_out, int out_size) {
    const float* x      = (const float*)d_in[0];
    const float* W1     = (const float*)d_in[1];
    const float* b1     = (const float*)d_in[2];
    const float* W2     = (const float*)d_in[3];
    const float* b2     = (const float*)d_in[4];
    const int*   assign = (const int*)d_in[5];
    const int*   kp     = (n_in >= 7) ? (const int*)d_in[6] : nullptr;
    float* out = (float*)d_out;

    k_zero<<<1024, 256>>>(out, out_size);
    k_detect<<<16, 256>>>(assign);
    k_build<<<16, 256>>>(assign);
    k_tiles<<<1, 32>>>();

    // fp16 conversion prepass (RNE): x, W1 only (W2 fused into GEMM1)
    __half *xh, *w1h, *w2h;
    cudaGetSymbolAddress((void**)&xh,  g_xh);
    cudaGetSymbolAddress((void**)&w1h, g_w1h);
    cudaGetSymbolAddress((void**)&w2h, g_w2h);
    k_tohalf8<<<512,  256>>>(xh,  x,  NTOK * Dq / 8);
    k_tohalf8<<<4096, 256>>>(w1h, W1, Eq * Dq * Hq / 8);

    cudaFuncSetAttribute(k_gemm_f16<Dq, Hq, true>,
                         cudaFuncAttributeMaxDynamicSharedMemorySize, SMEM_TOTAL);
    cudaFuncSetAttribute(k_gemm_f16<Hq, Dq, false>,
                         cudaFuncAttributeMaxDynamicSharedMemorySize, SMEM_TOTAL);

    // GEMM1: [rows,1024] @ [1024,4096] -> relu -> g_hh (fp16)
    //         + fused W2 fp32->fp16 conversion riding in idle DRAM cycles
    dim3 g1(Hq / 128, MAXTIL, 1);
    k_gemm_f16<Dq, Hq, true><<<g1, 256, SMEM_TOTAL>>>(
        xh, w1h, b1, nullptr, nullptr,
        W2, w2h, Eq * Hq * Dq / 8);

    // GEMM2: [rows,4096] @ [4096,1024] -> scatter-add out
    dim3 g2(Dq / 128, MAXTIL, 1);
    k_gemm_f16<Hq, Dq, false><<<g2, 256, SMEM_TOTAL>>>(
        nullptr, w2h, b2, out, kp,
        nullptr, nullptr, 0);
}

// round 14
// speedup vs baseline: 1.9875x; 1.0802x over previous
#include <cuda_runtime.h>
#include <cuda_fp16.h>
#include <cstdint>

// Problem constants (fixed for MoELayer_20761871908984)
#define Bq     4
#define Sq     1024
#define Dq     1024
#define Hq     4096
#define Eq     8
#define Kq     2
#define NTOK   (Bq * Sq)        // 4096 tokens
#define MAXROW (NTOK * Kq)      // 8192 max (token, expert) rows
#define MAXTIL 72               // >= sum ceil(cnt_e/128) (bound 71)

// -------- device-global scratch (no runtime allocation allowed) --------
__device__ int    g_counts[Eq];
__device__ int    g_lists[Eq][NTOK];
__device__ int    g_odd_nonzero;             // !=0 -> assign int32; ==0 -> int64
__device__ int    g_tile_e[MAXTIL];
__device__ int    g_tile_m[MAXTIL];
__device__ int    g_base[Eq];
__device__ int    g_ntiles;
__device__ __half g_xh [(size_t)NTOK * Dq];       //   8 MB x  (fp16 RNE)
__device__ __half g_hh [(size_t)MAXROW * Hq];     //  64 MB hidden (fp16 RNE)
__device__ __half g_w1h[(size_t)Eq * Dq * Hq];    //  64 MB W1 (fp16 RNE)
__device__ __half g_w2h[(size_t)Eq * Hq * Dq];    //  64 MB W2 (fp16 RNE)

// ---------------------------------------------------------------------
__global__ void k_zero(float* __restrict__ out, int n) {
    int i = blockIdx.x * blockDim.x + threadIdx.x;
    int stride = gridDim.x * blockDim.x;
    float4 z = make_float4(0.f, 0.f, 0.f, 0.f);
    int n4 = n >> 2;
    for (int j = i; j < n4; j += stride)
        reinterpret_cast<float4*>(out)[j] = z;
    for (int j = (n4 << 2) + i; j < n; j += stride)
        out[j] = 0.f;
    if (i == 0) {
        g_odd_nonzero = 0;
#pragma unroll
        for (int e = 0; e < Eq; e++) g_counts[e] = 0;
    }
}

__global__ void k_detect(const int* __restrict__ a32) {
    int i = blockIdx.x * blockDim.x + threadIdx.x;   // [0, 4096)
    int idx = 2 * i + 1;
    if (idx < NTOK * Kq) {
        if (a32[idx] != 0) atomicOr(&g_odd_nonzero, 1);
    }
}

__global__ void k_build(const int* __restrict__ a32) {
    int t = blockIdx.x * blockDim.x + threadIdx.x;
    if (t >= NTOK) return;
    int is64 = (g_odd_nonzero == 0);
    unsigned mask = 0;
#pragma unroll
    for (int j = 0; j < Kq; j++) {
        int e;
        if (is64) e = a32[(t * Kq + j) * 2];
        else      e = a32[t * Kq + j];
        mask |= 1u << (e & (Eq - 1));
    }
    while (mask) {
        int e = __ffs(mask) - 1;
        mask &= mask - 1;
        int p = atomicAdd(&g_counts[e], 1);
        g_lists[e][p] = t;
    }
}

// Build the (expert, m-tile) work table + per-expert row bases.
__global__ void k_tiles() {
    if (threadIdx.x != 0 || blockIdx.x != 0) return;
    int base = 0, nt = 0;
#pragma unroll
    for (int e = 0; e < Eq; e++) {
        int cnt = g_counts[e];
        g_base[e] = base;
        for (int m0 = 0; m0 < cnt && nt < MAXTIL; m0 += 128) {
            g_tile_e[nt] = e;
            g_tile_m[nt] = m0;
            nt++;
        }
        base += cnt;
    }
    g_ntiles = nt;
}

// Prepass: fp32 -> fp16 (RNE), 8 elems/iter, 16B stores.
__global__ void k_tohalf8(__half* __restrict__ dst, const float* __restrict__ src, int n8) {
    int i = blockIdx.x * blockDim.x + threadIdx.x;
    int stride = gridDim.x * blockDim.x;
    for (; i < n8; i += stride) {
        float4 a = reinterpret_cast<const float4*>(src)[2 * i];
        float4 b = reinterpret_cast<const float4*>(src)[2 * i + 1];
        __half2 h0 = __floats2half2_rn(a.x, a.y);
        __half2 h1 = __floats2half2_rn(a.z, a.w);
        __half2 h2 = __floats2half2_rn(b.x, b.y);
        __half2 h3 = __floats2half2_rn(b.z, b.w);
        uint4 o;
        o.x = reinterpret_cast<unsigned&>(h0);
        o.y = reinterpret_cast<unsigned&>(h1);
        o.z = reinterpret_cast<unsigned&>(h2);
        o.w = reinterpret_cast<unsigned&>(h3);
        reinterpret_cast<uint4*>(dst)[i] = o;
    }
}

// ---------------------------------------------------------------------
// fp16 MMA + ldmatrix + cp.async helpers
// ---------------------------------------------------------------------
__device__ __forceinline__ void mma_f16(float& d0, float& d1, float& d2, float& d3,
                                        unsigned a0, unsigned a1, unsigned a2, unsigned a3,
                                        unsigned b0, unsigned b1) {
    asm volatile(
        "mma.sync.aligned.m16n8k16.row.col.f32.f16.f16.f32 "
        "{%0,%1,%2,%3},{%4,%5,%6,%7},{%8,%9},{%0,%1,%2,%3};\n"
        : "+f"(d0), "+f"(d1), "+f"(d2), "+f"(d3)
        : "r"(a0), "r"(a1), "r"(a2), "r"(a3), "r"(b0), "r"(b1));
}

__device__ __forceinline__ void ldsm_x4(unsigned& r0, unsigned& r1, unsigned& r2, unsigned& r3,
                                        uint32_t addr) {
    asm volatile("ldmatrix.sync.aligned.m8n8.x4.shared.b16 {%0,%1,%2,%3}, [%4];\n"
                 : "=r"(r0), "=r"(r1), "=r"(r2), "=r"(r3) : "r"(addr));
}
__device__ __forceinline__ void ldsm_x4_t(unsigned& r0, unsigned& r1, unsigned& r2, unsigned& r3,
                                          uint32_t addr) {
    asm volatile("ldmatrix.sync.aligned.m8n8.x4.trans.shared.b16 {%0,%1,%2,%3}, [%4];\n"
                 : "=r"(r0), "=r"(r1), "=r"(r2), "=r"(r3) : "r"(addr));
}

__device__ __forceinline__ void cp_async16(uint32_t smem_addr, const void* gptr) {
    asm volatile("cp.async.cg.shared.global [%0], [%1], 16;\n"
                 :: "r"(smem_addr), "l"(gptr));
}
__device__ __forceinline__ void cp_commit() { asm volatile("cp.async.commit_group;\n"); }
__device__ __forceinline__ void cp_wait1()  { asm volatile("cp.async.wait_group 1;\n"); }
__device__ __forceinline__ void cp_wait0()  { asm volatile("cp.async.wait_group 0;\n"); }

// ---------------------------------------------------------------------
// Smem geometry (halves): BK=64 per stage, 3 stages.
// A: [128][ASTR=72] halves (144B rows) -> 8-row LDSM phase = partition
//    (row stride 36 words -> 4r mod 32 distinct over r=0..7).
// B: [64][BSTR=136] halves (272B rows) -> trans-LDSM phase = partition.
// ---------------------------------------------------------------------
#define ASTR 72
#define BSTR 136
#define NSTG 3
#define A_TILE_B (128 * ASTR * 2)          // 18432 B
#define B_TILE_B (64 * BSTR * 2)           // 17408 B
#define OFF_TOKS 0
#define OFF_A    512
#define OFF_B    (OFF_A + NSTG * A_TILE_B)           // 55808
#define SMEM_TOTAL (OFF_B + NSTG * B_TILE_B)         // 108032 (~105.5 KB)

// ---------------------------------------------------------------------
// fp16 grouped GEMM (mma.sync.m16n8k16).
// CTA tile 128x128, BK=64/stage, 256 threads, 8 warps 64x32.
// Optional fused tail: grid-stride fp32->fp16 conversion of cvt_src
// (W2) overlapped with GEMM1's tensor-bound execution.
// ---------------------------------------------------------------------
template<int KD, int ND, bool G1>
__global__ void __launch_bounds__(256, 2)
k_gemm_f16(const __half* __restrict__ Ain,    // G1: g_xh ; G2: g_hh
           const __half* __restrict__ W,      // fp16 [E][KD][ND]
           const float* __restrict__ bias,
           float* __restrict__ out,
           const int* __restrict__ kp,
           const float* __restrict__ cvt_src, // fused conversion (or null)
           __half* __restrict__ cvt_dst,
           int cvt_n8)
{
    constexpr int NK = KD / 64;
    const int ti = blockIdx.y;

    if (ti < g_ntiles) {
        const int e    = g_tile_e[ti];
        const int m0   = g_tile_m[ti];
        const int cnt  = g_counts[e];
        const int base = g_base[e];
        const int n0   = blockIdx.x * 128;

        extern __shared__ __align__(16) char smem[];
        int* toks = reinterpret_cast<int*>(smem + OFF_TOKS);

        const int tid  = threadIdx.x;
        const int lane = tid & 31;
        const int wid  = tid >> 5;
        const int wm   = wid >> 2;     // 0..1  (64-row band)
        const int wn   = wid & 3;      // 0..3  (32-col band)
        const int g    = lane >> 2;    // 0..7
        const int c    = lane & 3;     // 0..3

        if (tid < 128) {
            int row = m0 + tid;
            toks[tid] = (row < cnt) ? g_lists[e][row] : 0;
        }
        __syncthreads();

        const uint32_t sb  = (uint32_t)__cvta_generic_to_shared(smem);
        const uint32_t sbA = sb + OFF_A;
        const uint32_t sbB = sb + OFF_B;

        // ---- A staging: 4 chunks/thread. m = tid>>3 + 32i, aq = tid&7 ----
        const int aq = tid & 7;
        const __half* aSrc[4];
        uint32_t aDst[4];
#pragma unroll
        for (int i = 0; i < 4; i++) {
            int m = (tid >> 3) + 32 * i;
            int row = m0 + m;
            if (G1) aSrc[i] = Ain + (size_t)toks[m] * KD + 8 * aq;
            else    aSrc[i] = g_hh + (size_t)((row < cnt) ? base + row : base) * KD + 8 * aq;
            aDst[i] = (uint32_t)(m * (ASTR * 2) + aq * 16);
        }
        // ---- B staging: 4 chunks/thread. k = tid>>4 + 16i, nq = tid&15 ----
        const int bnq = tid & 15;
        const int bk0 = tid >> 4;
        const __half* Wp = W + (size_t)e * KD * ND;

        auto load_stage = [&](int kt, int buf) {
            const int k0 = kt * 64;
            const uint32_t dA = sbA + buf * A_TILE_B;
            const uint32_t dB = sbB + buf * B_TILE_B;
#pragma unroll
            for (int i = 0; i < 4; i++)
                cp_async16(dA + aDst[i], aSrc[i] + k0);
#pragma unroll
            for (int i = 0; i < 4; i++) {
                int k = bk0 + 16 * i;
                cp_async16(dB + (uint32_t)(k * (BSTR * 2) + bnq * 16),
                           Wp + (size_t)(k0 + k) * ND + n0 + 8 * bnq);
            }
            cp_commit();
        };

        float acc[4][4][4];
#pragma unroll
        for (int i = 0; i < 4; i++)
#pragma unroll
            for (int j = 0; j < 4; j++)
#pragma unroll
                for (int r = 0; r < 4; r++) acc[i][j][r] = 0.f;

        load_stage(0, 0);
        load_stage(1, 1);

        const int lrow  = wm * 64 + (lane & 15);
        const int lakb  = (lane >> 4) * 16;
        const int bkrow = (lane & 7) + ((lane >> 4) << 3);
        const int bnb0  = ((lane >> 3) & 1) * 16 + (wn * 32) * 2;

        for (int kt = 0; kt < NK; kt++) {
            const int buf = kt % NSTG;
            if (kt + 1 < NK) cp_wait1(); else cp_wait0();
            __syncthreads();
            if (kt + 2 < NK) load_stage(kt + 2, (kt + 2) % NSTG);

            const uint32_t Ab = sbA + buf * A_TILE_B;
            const uint32_t Bb = sbB + buf * B_TILE_B;

#pragma unroll
            for (int h = 0; h < 4; h++) {            // four 16-k steps of BK=64
                unsigned b0[4], b1[4];
#pragma unroll
                for (int t = 0; t < 2; t++) {
                    unsigned r0, r1, r2, r3;
                    uint32_t baddr = Bb + (uint32_t)((h * 16 + bkrow) * (BSTR * 2)
                                                     + bnb0 + t * 32);
                    ldsm_x4_t(r0, r1, r2, r3, baddr);
                    b0[2 * t]     = r0;  b0[2 * t + 1] = r1;
                    b1[2 * t]     = r2;  b1[2 * t + 1] = r3;
                }
#pragma unroll
                for (int i = 0; i < 4; i++) {
                    unsigned a0, a1, a2, a3;
                    uint32_t aaddr = Ab + (uint32_t)((lrow + i * 16) * (ASTR * 2)
                                                     + h * 32 + lakb);
                    ldsm_x4(a0, a1, a2, a3, aaddr);
#pragma unroll
                    for (int j = 0; j < 4; j++)
                        mma_f16(acc[i][j][0], acc[i][j][1], acc[i][j][2], acc[i][j][3],
                                a0, a1, a2, a3, b0[j], b1[j]);
                }
            }
        }

        // ---- epilogue ----
        if (G1) {
#pragma unroll
            for (int j = 0; j < 4; j++) {
                int col = n0 + wn * 32 + j * 8 + 2 * c;
                float bv0 = __ldg(bias + (size_t)e * ND + col);
                float bv1 = __ldg(bias + (size_t)e * ND + col + 1);
#pragma unroll
                for (int i = 0; i < 4; i++) {
                    int r0 = m0 + wm * 64 + i * 16 + g;
                    if (r0 < cnt) {
                        __half2 v = __floats2half2_rn(fmaxf(acc[i][j][0] + bv0, 0.f),
                                                      fmaxf(acc[i][j][1] + bv1, 0.f));
                        *reinterpret_cast<__half2*>(&g_hh[(size_t)(base + r0) * ND + col]) = v;
                    }
                    int r1 = r0 + 8;
                    if (r1 < cnt) {
                        __half2 v = __floats2half2_rn(fmaxf(acc[i][j][2] + bv0, 0.f),
                                                      fmaxf(acc[i][j][3] + bv1, 0.f));
                        *reinterpret_cast<__half2*>(&g_hh[(size_t)(base + r1) * ND + col]) = v;
                    }
                }
            }
        } else {
            int kv = kp ? __ldg(kp) : Kq;
            if (kv <= 0) kv = Kq;
            float inv_k = 1.0f / (float)kv;
#pragma unroll
            for (int j = 0; j < 4; j++) {
                int col = n0 + wn * 32 + j * 8 + 2 * c;
                float bv0 = __ldg(bias + (size_t)e * ND + col);
                float bv1 = __ldg(bias + (size_t)e * ND + col + 1);
#pragma unroll
                for (int i = 0; i < 4; i++) {
                    int r0 = m0 + wm * 64 + i * 16 + g;
                    if (r0 < cnt) {
                        float* op = out + (size_t)toks[r0 - m0] * ND + col;
                        atomicAdd(op,     (acc[i][j][0] + bv0) * inv_k);
                        atomicAdd(op + 1, (acc[i][j][1] + bv1) * inv_k);
                    }
                    int r1 = r0 + 8;
                    if (r1 < cnt) {
                        float* op = out + (size_t)toks[r1 - m0] * ND + col;
                        atomicAdd(op,     (acc[i][j][2] + bv0) * inv_k);
                        atomicAdd(op + 1, (acc[i][j][3] + bv1) * inv_k);
                    }
                }
            }
        }
    }

    // ---- fused conversion tail (all CTAs, incl. early-return ones) ----
    if (cvt_src) {
        int gtid = (blockIdx.y * gridDim.x + blockIdx.x) * blockDim.x + threadIdx.x;
        int gstride = gridDim.x * gridDim.y * blockDim.x;
        for (int i = gtid; i < cvt_n8; i += gstride) {
            float4 a = reinterpret_cast<const float4*>(cvt_src)[2 * i];
            float4 b = reinterpret_cast<const float4*>(cvt_src)[2 * i + 1];
            __half2 h0 = __floats2half2_rn(a.x, a.y);
            __half2 h1 = __floats2half2_rn(a.z, a.w);
            __half2 h2 = __floats2half2_rn(b.x, b.y);
            __half2 h3 = __floats2half2_rn(b.z, b.w);
            uint4 o;
            o.x = reinterpret_cast<unsigned&>(h0);
            o.y = reinterpret_cast<unsigned&>(h1);
            o.z = reinterpret_cast<unsigned&>(h2);
            o.w = reinterpret_cast<unsigned&>(h3);
            reinterpret_cast<uint4*>(cvt_dst)[i] = o;
        }
    }
}

// ---------------------------------------------------------------------
// launch
// ---------------------------------------------------------------------
extern "C" void kernel_launch(void* const* d_in, const int* in_sizes, int n_in,
                              void* d_out, int out_size) {
    const float* x      = (const float*)d_in[0];
    const float* W1     = (const float*)d_in[1];
    const float* b1     = (const float*)d_in[2];
    const float* W2     = (const float*)d_in[3];
    const float* b2     = (const float*)d_in[4];
    const int*   assign = (const int*)d_in[5];
    const int*   kp     = (n_in >= 7) ? (const int*)d_in[6] : nullptr;
    float* out = (float*)d_out;

    k_zero<<<1024, 256>>>(out, out_size);
    k_detect<<<16, 256>>>(assign);
    k_build<<<16, 256>>>(assign);
    k_tiles<<<1, 32>>>();

    // fp16 conversion prepass (RNE): x, W1 only (W2 fused into GEMM1)
    __half *xh, *w1h, *w2h;
    cudaGetSymbolAddress((void**)&xh,  g_xh);
    cudaGetSymbolAddress((void**)&w1h, g_w1h);
    cudaGetSymbolAddress((void**)&w2h, g_w2h);
    k_tohalf8<<<512,  256>>>(xh,  x,  NTOK * Dq / 8);
    k_tohalf8<<<4096, 256>>>(w1h, W1, Eq * Dq * Hq / 8);

    cudaFuncSetAttribute(k_gemm_f16<Dq, Hq, true>,
                         cudaFuncAttributeMaxDynamicSharedMemorySize, SMEM_TOTAL);
    cudaFuncSetAttribute(k_gemm_f16<Hq, Dq, false>,
                         cudaFuncAttributeMaxDynamicSharedMemorySize, SMEM_TOTAL);

    // GEMM1: [rows,1024] @ [1024,4096] -> relu -> g_hh (fp16)
    //         + fused W2 fp32->fp16 conversion riding in idle DRAM cycles
    dim3 g1(Hq / 128, MAXTIL, 1);
    k_gemm_f16<Dq, Hq, true><<<g1, 256, SMEM_TOTAL>>>(
        xh, w1h, b1, nullptr, nullptr,
        W2, w2h, Eq * Hq * Dq / 8);

    // GEMM2: [rows,4096] @ [4096,1024] -> scatter-add out
    dim3 g2(Dq / 128, MAXTIL, 1);
    k_gemm_f16<Hq, Dq, false><<<g2, 256, SMEM_TOTAL>>>(
        nullptr, w2h, b2, out, kp,
        nullptr, nullptr, 0);
}

// round 15
// speedup vs baseline: 2.0159x; 1.0143x over previous
#include <cuda_runtime.h>
#include <cuda_fp16.h>
#include <cstdint>

// Problem constants (fixed for MoELayer_20761871908984)
#define Bq     4
#define Sq     1024
#define Dq     1024
#define Hq     4096
#define Eq     8
#define Kq     2
#define NTOK   (Bq * Sq)        // 4096 tokens
#define MAXROW (NTOK * Kq)      // 8192 max (token, expert) rows
#define MAXTIL 72               // >= sum ceil(cnt_e/128) (bound 71)

// -------- device-global scratch (no runtime allocation allowed) --------
__device__ int    g_counts[Eq];
__device__ int    g_lists[Eq][NTOK];
__device__ int    g_odd_nonzero;             // sticky: 0 -> int64, 1 -> int32
__device__ int    g_done;                    // k_build completion counter
__device__ int    g_tile_e[MAXTIL];
__device__ int    g_tile_m[MAXTIL];
__device__ int    g_base[Eq];
__device__ int    g_ntiles;
__device__ __half g_xh [(size_t)NTOK * Dq];       //   8 MB x  (fp16 RNE)
__device__ __half g_hh [(size_t)MAXROW * Hq];     //  64 MB hidden (fp16 RNE)
__device__ __half g_w1h[(size_t)Eq * Dq * Hq];    //  64 MB W1 (fp16 RNE)
__device__ __half g_w2h[(size_t)Eq * Hq * Dq];    //  64 MB W2 (fp16 RNE)

// ---------------------------------------------------------------------
// k_prep: all independent front-end work in ONE launch.
//   - zero out
//   - detect assign width (sticky g_odd_nonzero; no reset needed)
//   - convert x -> fp16
//   - convert W1 -> fp16
//   - reset g_counts / g_done
// ---------------------------------------------------------------------
__global__ void k_prep(float* __restrict__ out, int n_out4,
                       const float* __restrict__ x,
                       const float* __restrict__ W1,
                       const int* __restrict__ a32) {
    const int i = blockIdx.x * blockDim.x + threadIdx.x;
    const int stride = gridDim.x * blockDim.x;

    if (i == 0) {
#pragma unroll
        for (int e = 0; e < Eq; e++) g_counts[e] = 0;
        g_done = 0;
    }

    // detect: odd 32-bit words nonzero <=> int32 layout
    if (i < NTOK * Kq / 2) {
        if (a32[2 * i + 1] != 0) atomicOr(&g_odd_nonzero, 1);
    }

    // zero output
    float4 z = make_float4(0.f, 0.f, 0.f, 0.f);
    for (int j = i; j < n_out4; j += stride)
        reinterpret_cast<float4*>(out)[j] = z;

    // x -> fp16 (8 elems/iter)
    const int nx8 = NTOK * Dq / 8;
    for (int j = i; j < nx8; j += stride) {
        float4 a = reinterpret_cast<const float4*>(x)[2 * j];
        float4 b = reinterpret_cast<const float4*>(x)[2 * j + 1];
        __half2 h0 = __floats2half2_rn(a.x, a.y);
        __half2 h1 = __floats2half2_rn(a.z, a.w);
        __half2 h2 = __floats2half2_rn(b.x, b.y);
        __half2 h3 = __floats2half2_rn(b.z, b.w);
        uint4 o;
        o.x = reinterpret_cast<unsigned&>(h0);
        o.y = reinterpret_cast<unsigned&>(h1);
        o.z = reinterpret_cast<unsigned&>(h2);
        o.w = reinterpret_cast<unsigned&>(h3);
        reinterpret_cast<uint4*>(g_xh)[j] = o;
    }

    // W1 -> fp16 (8 elems/iter)
    const int nw8 = Eq * Dq * Hq / 8;
    for (int j = i; j < nw8; j += stride) {
        float4 a = reinterpret_cast<const float4*>(W1)[2 * j];
        float4 b = reinterpret_cast<const float4*>(W1)[2 * j + 1];
        __half2 h0 = __floats2half2_rn(a.x, a.y);
        __half2 h1 = __floats2half2_rn(a.z, a.w);
        __half2 h2 = __floats2half2_rn(b.x, b.y);
        __half2 h3 = __floats2half2_rn(b.z, b.w);
        uint4 o;
        o.x = reinterpret_cast<unsigned&>(h0);
        o.y = reinterpret_cast<unsigned&>(h1);
        o.z = reinterpret_cast<unsigned&>(h2);
        o.w = reinterpret_cast<unsigned&>(h3);
        reinterpret_cast<uint4*>(g_w1h)[j] = o;
    }
}

// ---------------------------------------------------------------------
// k_build: per-expert token lists; LAST block also builds the tile table.
// ---------------------------------------------------------------------
__global__ void k_build(const int* __restrict__ a32) {
    int t = blockIdx.x * blockDim.x + threadIdx.x;
    if (t < NTOK) {
        int is64 = (g_odd_nonzero == 0);
        unsigned mask = 0;
#pragma unroll
        for (int j = 0; j < Kq; j++) {
            int e;
            if (is64) e = a32[(t * Kq + j) * 2];
            else      e = a32[t * Kq + j];
            mask |= 1u << (e & (Eq - 1));
        }
        while (mask) {
            int e = __ffs(mask) - 1;
            mask &= mask - 1;
            int p = atomicAdd(&g_counts[e], 1);
            g_lists[e][p] = t;
        }
    }
    __syncthreads();
    if (threadIdx.x == 0) {
        __threadfence();
        int done = atomicAdd(&g_done, 1);
        if (done == (int)gridDim.x - 1) {
            // all blocks' count atomics are globally visible
            int base = 0, nt = 0;
#pragma unroll
            for (int e = 0; e < Eq; e++) {
                int cnt = g_counts[e];
                g_base[e] = base;
                for (int m0 = 0; m0 < cnt && nt < MAXTIL; m0 += 128) {
                    g_tile_e[nt] = e;
                    g_tile_m[nt] = m0;
                    nt++;
                }
                base += cnt;
            }
            g_ntiles = nt;
        }
    }
}

// ---------------------------------------------------------------------
// fp16 MMA + ldmatrix + cp.async helpers
// ---------------------------------------------------------------------
__device__ __forceinline__ void mma_f16(float& d0, float& d1, float& d2, float& d3,
                                        unsigned a0, unsigned a1, unsigned a2, unsigned a3,
                                        unsigned b0, unsigned b1) {
    asm volatile(
        "mma.sync.aligned.m16n8k16.row.col.f32.f16.f16.f32 "
        "{%0,%1,%2,%3},{%4,%5,%6,%7},{%8,%9},{%0,%1,%2,%3};\n"
        : "+f"(d0), "+f"(d1), "+f"(d2), "+f"(d3)
        : "r"(a0), "r"(a1), "r"(a2), "r"(a3), "r"(b0), "r"(b1));
}

__device__ __forceinline__ void ldsm_x4(unsigned& r0, unsigned& r1, unsigned& r2, unsigned& r3,
                                        uint32_t addr) {
    asm volatile("ldmatrix.sync.aligned.m8n8.x4.shared.b16 {%0,%1,%2,%3}, [%4];\n"
                 : "=r"(r0), "=r"(r1), "=r"(r2), "=r"(r3) : "r"(addr));
}
__device__ __forceinline__ void ldsm_x4_t(unsigned& r0, unsigned& r1, unsigned& r2, unsigned& r3,
                                          uint32_t addr) {
    asm volatile("ldmatrix.sync.aligned.m8n8.x4.trans.shared.b16 {%0,%1,%2,%3}, [%4];\n"
                 : "=r"(r0), "=r"(r1), "=r"(r2), "=r"(r3) : "r"(addr));
}

__device__ __forceinline__ void cp_async16(uint32_t smem_addr, const void* gptr) {
    asm volatile("cp.async.cg.shared.global [%0], [%1], 16;\n"
                 :: "r"(smem_addr), "l"(gptr));
}
__device__ __forceinline__ void cp_commit() { asm volatile("cp.async.commit_group;\n"); }
__device__ __forceinline__ void cp_wait1()  { asm volatile("cp.async.wait_group 1;\n"); }
__device__ __forceinline__ void cp_wait0()  { asm volatile("cp.async.wait_group 0;\n"); }

// ---------------------------------------------------------------------
// Smem geometry (halves): BK=64 per stage, 3 stages.
// A: [128][ASTR=72] halves -> 8-row LDSM phase = partition.
// B: [64][BSTR=136] halves -> trans-LDSM phase = partition.
// ---------------------------------------------------------------------
#define ASTR 72
#define BSTR 136
#define NSTG 3
#define A_TILE_B (128 * ASTR * 2)          // 18432 B
#define B_TILE_B (64 * BSTR * 2)           // 17408 B
#define OFF_TOKS 0
#define OFF_A    512
#define OFF_B    (OFF_A + NSTG * A_TILE_B)           // 55808
#define SMEM_TOTAL (OFF_B + NSTG * B_TILE_B)         // 108032 (~105.5 KB)

// ---------------------------------------------------------------------
// fp16 grouped GEMM (mma.sync.m16n8k16).
// CTA tile 128x128, BK=64/stage, 256 threads, 8 warps 64x32.
// Optional fused tail: grid-stride fp32->fp16 conversion of cvt_src (W2).
// ---------------------------------------------------------------------
template<int KD, int ND, bool G1>
__global__ void __launch_bounds__(256, 2)
k_gemm_f16(const __half* __restrict__ Ain,    // G1: g_xh ; G2: g_hh
           const __half* __restrict__ W,      // fp16 [E][KD][ND]
           const float* __restrict__ bias,
           float* __restrict__ out,
           const int* __restrict__ kp,
           const float* __restrict__ cvt_src, // fused conversion (or null)
           __half* __restrict__ cvt_dst,
           int cvt_n8)
{
    constexpr int NK = KD / 64;
    const int ti = blockIdx.y;

    if (ti < g_ntiles) {
        const int e    = g_tile_e[ti];
        const int m0   = g_tile_m[ti];
        const int cnt  = g_counts[e];
        const int base = g_base[e];
        const int n0   = blockIdx.x * 128;

        extern __shared__ __align__(16) char smem[];
        int* toks = reinterpret_cast<int*>(smem + OFF_TOKS);

        const int tid  = threadIdx.x;
        const int lane = tid & 31;
        const int wid  = tid >> 5;
        const int wm   = wid >> 2;     // 0..1  (64-row band)
        const int wn   = wid & 3;      // 0..3  (32-col band)
        const int g    = lane >> 2;    // 0..7
        const int c    = lane & 3;     // 0..3

        if (tid < 128) {
            int row = m0 + tid;
            toks[tid] = (row < cnt) ? g_lists[e][row] : 0;
        }
        __syncthreads();

        const uint32_t sb  = (uint32_t)__cvta_generic_to_shared(smem);
        const uint32_t sbA = sb + OFF_A;
        const uint32_t sbB = sb + OFF_B;

        // ---- A staging: 4 chunks/thread. m = tid>>3 + 32i, aq = tid&7 ----
        const int aq = tid & 7;
        const __half* aSrc[4];
        uint32_t aDst[4];
#pragma unroll
        for (int i = 0; i < 4; i++) {
            int m = (tid >> 3) + 32 * i;
            int row = m0 + m;
            if (G1) aSrc[i] = Ain + (size_t)toks[m] * KD + 8 * aq;
            else    aSrc[i] = g_hh + (size_t)((row < cnt) ? base + row : base) * KD + 8 * aq;
            aDst[i] = (uint32_t)(m * (ASTR * 2) + aq * 16);
        }
        // ---- B staging: 4 chunks/thread. k = tid>>4 + 16i, nq = tid&15 ----
        const int bnq = tid & 15;
        const int bk0 = tid >> 4;
        const __half* Wp = W + (size_t)e * KD * ND;

        auto load_stage = [&](int kt, int buf) {
            const int k0 = kt * 64;
            const uint32_t dA = sbA + buf * A_TILE_B;
            const uint32_t dB = sbB + buf * B_TILE_B;
#pragma unroll
            for (int i = 0; i < 4; i++)
                cp_async16(dA + aDst[i], aSrc[i] + k0);
#pragma unroll
            for (int i = 0; i < 4; i++) {
                int k = bk0 + 16 * i;
                cp_async16(dB + (uint32_t)(k * (BSTR * 2) + bnq * 16),
                           Wp + (size_t)(k0 + k) * ND + n0 + 8 * bnq);
            }
            cp_commit();
        };

        float acc[4][4][4];
#pragma unroll
        for (int i = 0; i < 4; i++)
#pragma unroll
            for (int j = 0; j < 4; j++)
#pragma unroll
                for (int r = 0; r < 4; r++) acc[i][j][r] = 0.f;

        load_stage(0, 0);
        load_stage(1, 1);

        const int lrow  = wm * 64 + (lane & 15);
        const int lakb  = (lane >> 4) * 16;
        const int bkrow = (lane & 7) + ((lane >> 4) << 3);
        const int bnb0  = ((lane >> 3) & 1) * 16 + (wn * 32) * 2;

        for (int kt = 0; kt < NK; kt++) {
            const int buf = kt % NSTG;
            if (kt + 1 < NK) cp_wait1(); else cp_wait0();
            __syncthreads();
            if (kt + 2 < NK) load_stage(kt + 2, (kt + 2) % NSTG);

            const uint32_t Ab = sbA + buf * A_TILE_B;
            const uint32_t Bb = sbB + buf * B_TILE_B;

#pragma unroll
            for (int h = 0; h < 4; h++) {            // four 16-k steps of BK=64
                unsigned b0[4], b1[4];
#pragma unroll
                for (int t = 0; t < 2; t++) {
                    unsigned r0, r1, r2, r3;
                    uint32_t baddr = Bb + (uint32_t)((h * 16 + bkrow) * (BSTR * 2)
                                                     + bnb0 + t * 32);
                    ldsm_x4_t(r0, r1, r2, r3, baddr);
                    b0[2 * t]     = r0;  b0[2 * t + 1] = r1;
                    b1[2 * t]     = r2;  b1[2 * t + 1] = r3;
                }
#pragma unroll
                for (int i = 0; i < 4; i++) {
                    unsigned a0, a1, a2, a3;
                    uint32_t aaddr = Ab + (uint32_t)((lrow + i * 16) * (ASTR * 2)
                                                     + h * 32 + lakb);
                    ldsm_x4(a0, a1, a2, a3, aaddr);
#pragma unroll
                    for (int j = 0; j < 4; j++)
                        mma_f16(acc[i][j][0], acc[i][j][1], acc[i][j][2], acc[i][j][3],
                                a0, a1, a2, a3, b0[j], b1[j]);
                }
            }
        }

        // ---- epilogue ----
        if (G1) {
#pragma unroll
            for (int j = 0; j < 4; j++) {
                int col = n0 + wn * 32 + j * 8 + 2 * c;
                float bv0 = __ldg(bias + (size_t)e * ND + col);
                float bv1 = __ldg(bias + (size_t)e * ND + col + 1);
#pragma unroll
                for (int i = 0; i < 4; i++) {
                    int r0 = m0 + wm * 64 + i * 16 + g;
                    if (r0 < cnt) {
                        __half2 v = __floats2half2_rn(fmaxf(acc[i][j][0] + bv0, 0.f),
                                                      fmaxf(acc[i][j][1] + bv1, 0.f));
                        *reinterpret_cast<__half2*>(&g_hh[(size_t)(base + r0) * ND + col]) = v;
                    }
                    int r1 = r0 + 8;
                    if (r1 < cnt) {
                        __half2 v = __floats2half2_rn(fmaxf(acc[i][j][2] + bv0, 0.f),
                                                      fmaxf(acc[i][j][3] + bv1, 0.f));
                        *reinterpret_cast<__half2*>(&g_hh[(size_t)(base + r1) * ND + col]) = v;
                    }
                }
            }
        } else {
            int kv = kp ? __ldg(kp) : Kq;
            if (kv <= 0) kv = Kq;
            float inv_k = 1.0f / (float)kv;
#pragma unroll
            for (int j = 0; j < 4; j++) {
                int col = n0 + wn * 32 + j * 8 + 2 * c;
                float bv0 = __ldg(bias + (size_t)e * ND + col);
                float bv1 = __ldg(bias + (size_t)e * ND + col + 1);
#pragma unroll
                for (int i = 0; i < 4; i++) {
                    int r0 = m0 + wm * 64 + i * 16 + g;
                    if (r0 < cnt) {
                        float* op = out + (size_t)toks[r0 - m0] * ND + col;
                        atomicAdd(op,     (acc[i][j][0] + bv0) * inv_k);
                        atomicAdd(op + 1, (acc[i][j][1] + bv1) * inv_k);
                    }
                    int r1 = r0 + 8;
                    if (r1 < cnt) {
                        float* op = out + (size_t)toks[r1 - m0] * ND + col;
                        atomicAdd(op,     (acc[i][j][2] + bv0) * inv_k);
                        atomicAdd(op + 1, (acc[i][j][3] + bv1) * inv_k);
                    }
                }
            }
        }
    }

    // ---- fused conversion tail (all CTAs, incl. early-return ones) ----
    if (cvt_src) {
        int gtid = (blockIdx.y * gridDim.x + blockIdx.x) * blockDim.x + threadIdx.x;
        int gstride = gridDim.x * gridDim.y * blockDim.x;
        for (int i = gtid; i < cvt_n8; i += gstride) {
            float4 a = reinterpret_cast<const float4*>(cvt_src)[2 * i];
            float4 b = reinterpret_cast<const float4*>(cvt_src)[2 * i + 1];
            __half2 h0 = __floats2half2_rn(a.x, a.y);
            __half2 h1 = __floats2half2_rn(a.z, a.w);
            __half2 h2 = __floats2half2_rn(b.x, b.y);
            __half2 h3 = __floats2half2_rn(b.z, b.w);
            uint4 o;
            o.x = reinterpret_cast<unsigned&>(h0);
            o.y = reinterpret_cast<unsigned&>(h1);
            o.z = reinterpret_cast<unsigned&>(h2);
            o.w = reinterpret_cast<unsigned&>(h3);
            reinterpret_cast<uint4*>(cvt_dst)[i] = o;
        }
    }
}

// ---------------------------------------------------------------------
// launch
// ---------------------------------------------------------------------
extern "C" void kernel_launch(void* const* d_in, const int* in_sizes, int n_in,
                              void* d_out, int out_size) {
    const float* x      = (const float*)d_in[0];
    const float* W1     = (const float*)d_in[1];
    const float* b1     = (const float*)d_in[2];
    const float* W2     = (const float*)d_in[3];
    const float* b2     = (const float*)d_in[4];
    const int*   assign = (const int*)d_in[5];
    const int*   kp     = (n_in >= 7) ? (const int*)d_in[6] : nullptr;
    float* out = (float*)d_out;

    __half *w2h;
    cudaGetSymbolAddress((void**)&w2h, g_w2h);
    __half *xh;
    cudaGetSymbolAddress((void**)&xh, g_xh);
    __half *w1h;
    cudaGetSymbolAddress((void**)&w1h, g_w1h);

    // 1) all independent front-end work in one wide launch
    k_prep<<<4096, 256>>>(out, out_size / 4, x, W1, assign);

    // 2) router lists + tile table (last-block)
    k_build<<<16, 256>>>(assign);

    cudaFuncSetAttribute(k_gemm_f16<Dq, Hq, true>,
                         cudaFuncAttributeMaxDynamicSharedMemorySize, SMEM_TOTAL);
    cudaFuncSetAttribute(k_gemm_f16<Hq, Dq, false>,
                         cudaFuncAttributeMaxDynamicSharedMemorySize, SMEM_TOTAL);

    // 3) GEMM1: [rows,1024] @ [1024,4096] -> relu -> g_hh (fp16)
    //            + fused W2 fp32->fp16 conversion in idle DRAM cycles
    dim3 g1(Hq / 128, MAXTIL, 1);
    k_gemm_f16<Dq, Hq, true><<<g1, 256, SMEM_TOTAL>>>(
        xh, w1h, b1, nullptr, nullptr,
        W2, w2h, Eq * Hq * Dq / 8);

    // 4) GEMM2: [rows,4096] @ [4096,1024] -> scatter-add out
    dim3 g2(Dq / 128, MAXTIL, 1);
    k_gemm_f16<Hq, Dq, false><<<g2, 256, SMEM_TOTAL>>>(
        nullptr, w2h, b2, out, kp,
        nullptr, nullptr, 0);
}